// round 12
// baseline (speedup 1.0000x reference)
#include <cuda_runtime.h>
#include <cuda_fp16.h>
#include <cstdint>

// B=2, T=2048, C=1024, H=16, D=64, causal MHA, fp32 in/out.
#define BB 2
#define TT 2048
#define CC 1024
#define HH 16
#define DD 64
#define MM (BB*TT)

typedef __half h16;

// ---------------- scratch (allocation-free) ----------------
__device__ h16 g_xh[MM*CC], g_xl[MM*CC];
__device__ h16 g_ah[MM*CC], g_al[MM*CC];
__device__ h16 g_wh[4*CC*CC], g_wl[4*CC*CC];   // [Wq|Wk|Wv|Wo] transposed [n][k]
__device__ h16 g_qh[BB*HH*TT*DD], g_ql[BB*HH*TT*DD];
__device__ h16 g_kh[BB*HH*TT*DD], g_kl[BB*HH*TT*DD];
__device__ h16 g_vh[BB*HH*TT*DD], g_vl[BB*HH*TT*DD];

// ---------------- helpers (sm_80-baseline PTX only) ----------------
__device__ __forceinline__ uint32_t smem_u32(const void* p) {
    return (uint32_t)__cvta_generic_to_shared(p);
}

#define CP16(dst, src) \
    asm volatile("cp.async.cg.shared.global [%0], [%1], 16;" :: "r"(dst), "l"(src) : "memory")
#define CP_COMMIT() asm volatile("cp.async.commit_group;" ::: "memory")
#define CP_WAIT(n)  asm volatile("cp.async.wait_group %0;" :: "n"(n) : "memory")

__device__ __forceinline__ void ldm4(uint32_t* r, uint32_t a) {
    asm volatile("ldmatrix.sync.aligned.m8n8.x4.shared.b16 {%0,%1,%2,%3}, [%4];"
                 : "=r"(r[0]), "=r"(r[1]), "=r"(r[2]), "=r"(r[3]) : "r"(a));
}
__device__ __forceinline__ void ldm4t(uint32_t* r, uint32_t a) {
    asm volatile("ldmatrix.sync.aligned.m8n8.x4.trans.shared.b16 {%0,%1,%2,%3}, [%4];"
                 : "=r"(r[0]), "=r"(r[1]), "=r"(r[2]), "=r"(r[3]) : "r"(a));
}
__device__ __forceinline__ void mma_f32(float* d, const uint32_t* a, const uint32_t* b) {
    asm volatile("mma.sync.aligned.m16n8k16.row.col.f32.f16.f16.f32 "
                 "{%0,%1,%2,%3}, {%4,%5,%6,%7}, {%8,%9}, {%0,%1,%2,%3};"
                 : "+f"(d[0]), "+f"(d[1]), "+f"(d[2]), "+f"(d[3])
                 : "r"(a[0]), "r"(a[1]), "r"(a[2]), "r"(a[3]), "r"(b[0]), "r"(b[1]));
}

__device__ __forceinline__ float2 h2f(uint32_t u) {
    __half2 h = *reinterpret_cast<__half2*>(&u);
    return __half22float2(h);
}
__device__ __forceinline__ uint32_t pk2h(float a, float b) {
    __half2 t = __floats2half2_rn(a, b);
    return *reinterpret_cast<uint32_t*>(&t);
}
__device__ __forceinline__ void split_st(h16* hi, h16* lo, size_t off, float a, float b) {
    uint32_t hp = pk2h(a, b);
    float2 back = h2f(hp);
    *(uint32_t*)(hi + off) = hp;
    *(uint32_t*)(lo + off) = pk2h(a - back.x, b - back.y);
}

// ---------------------------------------------------------------------------
__global__ void split_kernel(const float* __restrict__ x,
                             h16* __restrict__ hi, h16* __restrict__ lo) {
    int i = blockIdx.x * blockDim.x + threadIdx.x;
    float4 v = ((const float4*)x)[i];
    split_st(hi, lo, 4*(size_t)i,     v.x, v.y);
    split_st(hi, lo, 4*(size_t)i + 2, v.z, v.w);
}

// ---------------------------------------------------------------------------
__global__ void tsplit_kernel(const float* __restrict__ W0, const float* __restrict__ W1,
                              const float* __restrict__ W2, const float* __restrict__ W3,
                              h16* __restrict__ hi, h16* __restrict__ lo) {
    __shared__ float t[32][33];
    int tx = threadIdx.x, ty = threadIdx.y;          // (32, 8)
    int n0 = blockIdx.x * 32, k0 = blockIdx.y * 32;
    int z = blockIdx.z;
    const float* W = (z == 0) ? W0 : (z == 1) ? W1 : (z == 2) ? W2 : W3;
    h16* hz = hi + (size_t)z * CC * CC;
    h16* lz = lo + (size_t)z * CC * CC;
#pragma unroll
    for (int i = 0; i < 4; i++)
        t[ty + 8*i][tx] = W[(size_t)(k0 + ty + 8*i) * CC + n0 + tx];
    __syncthreads();
#pragma unroll
    for (int i = 0; i < 4; i++) {
        float v = t[tx][ty + 8*i];
        __half h = __float2half_rn(v);
        size_t o = (size_t)(n0 + ty + 8*i) * CC + k0 + tx;
        hz[o] = h;
        lz[o] = __float2half_rn(v - __half2float(h));
    }
}

// ---------------------------------------------------------------------------
// fp16x3 GEMM (uniform f32-acc): 128x128 tile, K-chunk 64, 2-stage cp.async.
// MODE 0: fused QKV (grid.x covers N=3072), split-fp16 out to [B,H,T,D].
// MODE 1: single GEMM (Wo), fp32 [M,N].
// ---------------------------------------------------------------------------
#define GSTG 65536
#define NKT  16

template<int MODE>
__global__ __launch_bounds__(256) void gemm_f16x3(
    const h16* __restrict__ Ah, const h16* __restrict__ Al,
    const h16* __restrict__ Bh, const h16* __restrict__ Bl,
    const float* __restrict__ bias0, const float* __restrict__ bias1,
    const float* __restrict__ bias2,
    float* __restrict__ outF,
    h16* __restrict__ o0h, h16* __restrict__ o0l,
    h16* __restrict__ o1h, h16* __restrict__ o1l,
    h16* __restrict__ o2h, h16* __restrict__ o2l)
{
    extern __shared__ char smraw[];
    const uint32_t sbase = smem_u32(smraw);

    int tid = threadIdx.x, lane = tid & 31, wid = tid >> 5;
    int wm = wid & 1, wn = wid >> 1;
    int m0 = blockIdx.y << 7, n0 = blockIdx.x << 7;

    const float* bias = bias0;
    h16 *oh = o0h, *ol = o0l;
    float scale = 1.0f;
    if (MODE == 0) {
        int sec = n0 >> 10;
        bias = (sec == 0) ? bias0 : (sec == 1) ? bias1 : bias2;
        oh   = (sec == 0) ? o0h   : (sec == 1) ? o1h   : o2h;
        ol   = (sec == 0) ? o0l   : (sec == 1) ? o1l   : o2l;
        // Q pre-scaled by (1/8)*log2(e): softmax runs in exp2 domain.
        scale = (sec == 0) ? 0.180336885f : 1.0f;
    }

    float acc[4][4][4] = {};

    auto load_stage = [&](int kt, int s) {
        uint32_t sb = sbase + (uint32_t)s * GSTG;
#pragma unroll
        for (int i = 0; i < 4; i++) {
            int id = tid + i*256;
            int r = id >> 3, c = id & 7;
            uint32_t phys = (uint32_t)(r*128 + ((c ^ (r & 7)) << 4));
            size_t ga = (size_t)(m0 + r)*CC + kt*64 + c*8;
            size_t gb = (size_t)(n0 + r)*CC + kt*64 + c*8;
            CP16(sb +         phys, Ah + ga);
            CP16(sb + 16384 + phys, Al + ga);
            CP16(sb + 32768 + phys, Bh + gb);
            CP16(sb + 49152 + phys, Bl + gb);
        }
        CP_COMMIT();
    };

    load_stage(0, 0);

    int ahalf = lane >> 4;
    int bhalf = (lane >> 3) & 1;
    int arow = wm*64 + (lane & 15);
    int brow = wn*32 + ((lane >> 4) << 3) + (lane & 7);

    for (int kt = 0; kt < NKT; kt++) {
        if (kt + 1 < NKT) { load_stage(kt + 1, (kt + 1) & 1); CP_WAIT(1); }
        else              { CP_WAIT(0); }
        __syncthreads();

        uint32_t sb = sbase + (uint32_t)(kt & 1) * GSTG;
#pragma unroll
        for (int kk = 0; kk < 4; kk++) {
            uint32_t aswz = (uint32_t)(((2*kk + ahalf) ^ (arow & 7)) << 4);
            uint32_t bswz = (uint32_t)(((2*kk + bhalf) ^ (brow & 7)) << 4);
            uint32_t ah4[4][4], al4[4][4], bh4[2][4], bl4[2][4];
#pragma unroll
            for (int mf = 0; mf < 4; mf++) {
                uint32_t off = (uint32_t)((arow + mf*16) * 128) + aswz;
                ldm4(ah4[mf], sb + off);
                ldm4(al4[mf], sb + 16384 + off);
            }
#pragma unroll
            for (int nh = 0; nh < 2; nh++) {
                uint32_t off = (uint32_t)((brow + nh*16) * 128) + bswz;
                ldm4(bh4[nh], sb + 32768 + off);
                ldm4(bl4[nh], sb + 49152 + off);
            }
#pragma unroll
            for (int mf = 0; mf < 4; mf++)
#pragma unroll
                for (int nf = 0; nf < 4; nf++) {
                    const uint32_t* ph = bh4[nf >> 1] + (nf & 1)*2;
                    const uint32_t* pl = bl4[nf >> 1] + (nf & 1)*2;
                    mma_f32(acc[mf][nf], ah4[mf], ph);
                    mma_f32(acc[mf][nf], ah4[mf], pl);
                    mma_f32(acc[mf][nf], al4[mf], ph);
                }
        }
        __syncthreads();
    }

    int g = lane >> 2, t2 = (lane & 3) * 2;
#pragma unroll
    for (int nf = 0; nf < 4; nf++) {
        int col = n0 + wn*32 + nf*8 + t2;
        int lc = col & (CC - 1);
        float2 bb = *(const float2*)(bias + lc);
#pragma unroll
        for (int mf = 0; mf < 4; mf++) {
            int m1 = m0 + wm*64 + mf*16 + g;
            float v0 = acc[mf][nf][0] + bb.x, v1 = acc[mf][nf][1] + bb.y;
            float v2 = acc[mf][nf][2] + bb.x, v3 = acc[mf][nf][3] + bb.y;
            if (MODE == 0) {
                int h = lc >> 6, d = lc & 63;
                int b1 = m1 >> 11, t1 = m1 & (TT - 1);
                size_t base = ((size_t)(b1*HH + h)*TT) * DD + d;
                split_st(oh, ol, base + (size_t)t1*DD,       v0*scale, v1*scale);
                split_st(oh, ol, base + (size_t)(t1 + 8)*DD, v2*scale, v3*scale);
            } else {
                *(float2*)(outF + (size_t)m1*CC + col)       = make_float2(v0, v1);
                *(float2*)(outF + (size_t)(m1 + 8)*CC + col) = make_float2(v2, v3);
            }
        }
    }
}

// ---------------------------------------------------------------------------
// Tensor-core causal flash attention, fp16x3, f32 accumulate, exp2 domain.
// q-tile 128, k-tile 128, Q frags resident, occ-1.
// Diagonal-tile pruning: on the last k-tile, warp w only computes its
// ngmax = w+1 16-key groups (statically unrolled, runtime-guarded).
// smem: Qh(16K) Ql(16K) | 2 stages x [Kh Kl Vh Vl](16K each) = 160KB.
// ---------------------------------------------------------------------------
__global__ __launch_bounds__(256) void attn_mma()
{
    extern __shared__ char smraw[];
    const uint32_t sb = smem_u32(smraw);
    const uint32_t QH = 0, QL = 16384, ST = 32768, STSZ = 65536;

    int tid = threadIdx.x, lane = tid & 31, w = tid >> 5;
    int bh = blockIdx.y;
    int qt = (int)gridDim.x - 1 - (int)blockIdx.x;   // heavy tiles first
    int q0 = qt * 128;
    int nkt = qt + 1;

    const h16* Qh = g_qh + (size_t)bh*TT*DD;
    const h16* Ql = g_ql + (size_t)bh*TT*DD;
    const h16* Kh = g_kh + (size_t)bh*TT*DD;
    const h16* Kl = g_kl + (size_t)bh*TT*DD;
    const h16* Vh = g_vh + (size_t)bh*TT*DD;
    const h16* Vl = g_vl + (size_t)bh*TT*DD;

    auto load_kv = [&](int kt, int s) {
        uint32_t base = sb + ST + (uint32_t)s * STSZ;
        int k0 = kt * 128;
#pragma unroll
        for (int i = 0; i < 4; i++) {
            int id = tid + i*256;
            int r = id >> 3, c = id & 7;
            uint32_t phys = (uint32_t)(r*128 + ((c ^ (r & 7)) << 4));
            size_t gsrc = (size_t)(k0 + r)*DD + c*8;
            CP16(base +         phys, Kh + gsrc);
            CP16(base + 16384 + phys, Kl + gsrc);
            CP16(base + 32768 + phys, Vh + gsrc);
            CP16(base + 49152 + phys, Vl + gsrc);
        }
        CP_COMMIT();
    };

    // Q tile (128 x 64) hi/lo
#pragma unroll
    for (int m = 0; m < 2; m++)
#pragma unroll
        for (int i = 0; i < 4; i++) {
            int id = tid + i*256;
            int r = id >> 3, c = id & 7;
            uint32_t dst = sb + (m ? QL : QH) + (uint32_t)(r*128 + ((c ^ (r & 7)) << 4));
            const h16* src = (m ? Ql : Qh) + (size_t)(q0 + r)*DD + c*8;
            CP16(dst, src);
        }
    CP_COMMIT();
    load_kv(0, 0);

    CP_WAIT(1);
    __syncthreads();

    // Q fragments (resident)
    uint32_t qfh[4][4], qfl[4][4];
    int arow = w*16 + (lane & 15), ahalf = lane >> 4;
#pragma unroll
    for (int kk = 0; kk < 4; kk++) {
        uint32_t off = (uint32_t)(arow*128 + (((2*kk + ahalf) ^ (arow & 7)) << 4));
        ldm4(qfh[kk], sb + QH + off);
        ldm4(qfl[kk], sb + QL + off);
    }

    float oacc[8][4] = {};
    float mrow0 = -1e30f, mrow1 = -1e30f;
    float lsum0 = 0.f, lsum1 = 0.f;

    int g = lane >> 2, t2 = (lane & 3) * 2;
    int r0g = q0 + 16*w + g, r1g = r0g + 8;
    int bhalf = (lane >> 3) & 1;
    int vi = lane >> 3, vr = lane & 7;

    for (int kt = 0; kt < nkt; kt++) {
        if (kt + 1 < nkt) { load_kv(kt + 1, (kt + 1) & 1); CP_WAIT(1); }
        else              { CP_WAIT(0); }
        __syncthreads();

        int k0 = kt * 128;
        uint32_t st = sb + ST + (uint32_t)(kt & 1) * STSZ;
        bool diag = (kt == nkt - 1);
        int ngmax = diag ? (w + 1) : 8;        // 16-key groups this warp needs

        // ---- S = Q K^T (pruned on diagonal) ----
        float sacc[16][4] = {};
#pragma unroll
        for (int kk = 0; kk < 4; kk++) {
#pragma unroll
            for (int ng = 0; ng < 8; ng++) {
                if (ng < ngmax) {
                    int brow = ng*16 + ((lane >> 4) << 3) + (lane & 7);
                    uint32_t off = (uint32_t)(brow*128 + (((2*kk + bhalf) ^ (brow & 7)) << 4));
                    uint32_t kh4[4], kl4[4];
                    ldm4(kh4, st + off);
                    ldm4(kl4, st + 16384 + off);
                    mma_f32(sacc[2*ng],   qfh[kk], kh4);
                    mma_f32(sacc[2*ng],   qfh[kk], kl4);
                    mma_f32(sacc[2*ng],   qfl[kk], kh4);
                    mma_f32(sacc[2*ng+1], qfh[kk], kh4 + 2);
                    mma_f32(sacc[2*ng+1], qfh[kk], kl4 + 2);
                    mma_f32(sacc[2*ng+1], qfl[kk], kh4 + 2);
                }
            }
        }

        // ---- causal mask (computed fragments only) ----
        if (diag) {
#pragma unroll
            for (int j = 0; j < 16; j++) {
                if (j < 2*ngmax) {
                    int col = k0 + 8*j + t2;
                    if (col     > r0g) sacc[j][0] = -1e30f;
                    if (col + 1 > r0g) sacc[j][1] = -1e30f;
                    if (col     > r1g) sacc[j][2] = -1e30f;
                    if (col + 1 > r1g) sacc[j][3] = -1e30f;
                }
            }
        }

        // ---- online softmax (exp2 domain) ----
        float tm0 = -1e30f, tm1 = -1e30f;
#pragma unroll
        for (int j = 0; j < 16; j++) {
            if (j < 2*ngmax) {
                tm0 = fmaxf(tm0, fmaxf(sacc[j][0], sacc[j][1]));
                tm1 = fmaxf(tm1, fmaxf(sacc[j][2], sacc[j][3]));
            }
        }
        tm0 = fmaxf(tm0, __shfl_xor_sync(0xffffffffu, tm0, 1));
        tm0 = fmaxf(tm0, __shfl_xor_sync(0xffffffffu, tm0, 2));
        tm1 = fmaxf(tm1, __shfl_xor_sync(0xffffffffu, tm1, 1));
        tm1 = fmaxf(tm1, __shfl_xor_sync(0xffffffffu, tm1, 2));
        float mn0 = fmaxf(mrow0, tm0), mn1 = fmaxf(mrow1, tm1);
        float c0 = exp2f(mrow0 - mn0), c1 = exp2f(mrow1 - mn1);
        mrow0 = mn0; mrow1 = mn1;

        float ps0 = 0.f, ps1 = 0.f;
        uint32_t pfh[8][4], pfl[8][4];
#pragma unroll
        for (int kc = 0; kc < 8; kc++) {
            if (kc < ngmax) {
#pragma unroll
                for (int jj = 0; jj < 2; jj++) {
                    int j = 2*kc + jj;
                    float p0 = exp2f(sacc[j][0] - mn0);
                    float p1 = exp2f(sacc[j][1] - mn0);
                    float p2 = exp2f(sacc[j][2] - mn1);
                    float p3 = exp2f(sacc[j][3] - mn1);
                    ps0 += p0 + p1; ps1 += p2 + p3;
                    uint32_t hp01 = pk2h(p0, p1);
                    uint32_t hp23 = pk2h(p2, p3);
                    float2 b01 = h2f(hp01), b23 = h2f(hp23);
                    pfh[kc][2*jj]   = hp01;
                    pfh[kc][2*jj+1] = hp23;
                    pfl[kc][2*jj]   = pk2h(p0 - b01.x, p1 - b01.y);
                    pfl[kc][2*jj+1] = pk2h(p2 - b23.x, p3 - b23.y);
                }
            }
        }
        lsum0 = lsum0 * c0 + ps0;
        lsum1 = lsum1 * c1 + ps1;
#pragma unroll
        for (int j = 0; j < 8; j++) {
            oacc[j][0] *= c0; oacc[j][1] *= c0;
            oacc[j][2] *= c1; oacc[j][3] *= c1;
        }

        // ---- O += P V (pruned on diagonal) ----
#pragma unroll
        for (int kc = 0; kc < 8; kc++) {
            if (kc < ngmax) {
#pragma unroll
                for (int dg = 0; dg < 4; dg++) {
                    int key = kc*16 + 8*(vi & 1) + vr;
                    int dc = 2*dg + (vi >> 1);
                    uint32_t off = (uint32_t)(key*128 + ((dc ^ (key & 7)) << 4));
                    uint32_t vh4[4], vl4[4];
                    ldm4t(vh4, st + 32768 + off);
                    ldm4t(vl4, st + 49152 + off);
                    mma_f32(oacc[2*dg],   pfh[kc], vh4);
                    mma_f32(oacc[2*dg],   pfh[kc], vl4);
                    mma_f32(oacc[2*dg],   pfl[kc], vh4);
                    mma_f32(oacc[2*dg+1], pfh[kc], vh4 + 2);
                    mma_f32(oacc[2*dg+1], pfh[kc], vl4 + 2);
                    mma_f32(oacc[2*dg+1], pfl[kc], vh4 + 2);
                }
            }
        }
        __syncthreads();
    }

    lsum0 += __shfl_xor_sync(0xffffffffu, lsum0, 1);
    lsum0 += __shfl_xor_sync(0xffffffffu, lsum0, 2);
    lsum1 += __shfl_xor_sync(0xffffffffu, lsum1, 1);
    lsum1 += __shfl_xor_sync(0xffffffffu, lsum1, 2);
    float inv0 = 1.f / lsum0, inv1 = 1.f / lsum1;

    int b = bh >> 4, h = bh & 15;
    size_t row0 = (size_t)(b*TT + r0g) * CC + h*DD;
    size_t row1 = (size_t)(b*TT + r1g) * CC + h*DD;
#pragma unroll
    for (int j = 0; j < 8; j++) {
        int d = 8*j + t2;
        split_st(g_ah, g_al, row0 + d, oacc[j][0]*inv0, oacc[j][1]*inv0);
        split_st(g_ah, g_al, row1 + d, oacc[j][2]*inv1, oacc[j][3]*inv1);
    }
}

// ---------------------------------------------------------------------------
extern "C" void kernel_launch(void* const* d_in, const int* in_sizes, int n_in,
                              void* d_out, int out_size)
{
    (void)in_sizes; (void)n_in; (void)out_size;
    const float* x  = (const float*)d_in[0];
    const float* Wq = (const float*)d_in[1];
    const float* bq = (const float*)d_in[2];
    const float* Wk = (const float*)d_in[3];
    const float* bk = (const float*)d_in[4];
    const float* Wv = (const float*)d_in[5];
    const float* bv = (const float*)d_in[6];
    const float* Wo = (const float*)d_in[7];
    const float* bo = (const float*)d_in[8];
    float* out = (float*)d_out;

    h16 *xh, *xl, *ah, *al, *wh, *wl, *qh, *ql, *kh, *kl, *vh, *vl;
    cudaGetSymbolAddress((void**)&xh, g_xh);
    cudaGetSymbolAddress((void**)&xl, g_xl);
    cudaGetSymbolAddress((void**)&ah, g_ah);
    cudaGetSymbolAddress((void**)&al, g_al);
    cudaGetSymbolAddress((void**)&wh, g_wh);
    cudaGetSymbolAddress((void**)&wl, g_wl);
    cudaGetSymbolAddress((void**)&qh, g_qh);
    cudaGetSymbolAddress((void**)&ql, g_ql);
    cudaGetSymbolAddress((void**)&kh, g_kh);
    cudaGetSymbolAddress((void**)&kl, g_kl);
    cudaGetSymbolAddress((void**)&vh, g_vh);
    cudaGetSymbolAddress((void**)&vl, g_vl);

    // 1. split x
    split_kernel<<<(MM*CC/4)/256, 256>>>(x, xh, xl);

    // 2. transpose+split all 4 weights (one launch)
    tsplit_kernel<<<dim3(CC/32, CC/32, 4), dim3(32, 8)>>>(Wq, Wk, Wv, Wo, wh, wl);

    // 3. fused QKV projection (N=3072); Q pre-scaled by log2e/8 (exp2 domain)
    const int gsm = 2 * GSTG;  // 128 KB
    cudaFuncSetAttribute(gemm_f16x3<0>, cudaFuncAttributeMaxDynamicSharedMemorySize, gsm);
    cudaFuncSetAttribute(gemm_f16x3<1>, cudaFuncAttributeMaxDynamicSharedMemorySize, gsm);
    gemm_f16x3<0><<<dim3(3*CC/128, MM/128), 256, gsm>>>(
        xh, xl, wh, wl, bq, bk, bv,
        nullptr, qh, ql, kh, kl, vh, vl);

    // 4. tensor-core flash attention (k-tile 128, diagonal-pruned)
    const int asm_sz = 32768 + 2*65536;   // 163840
    cudaFuncSetAttribute(attn_mma, cudaFuncAttributeMaxDynamicSharedMemorySize, asm_sz);
    attn_mma<<<dim3(TT/128, BB*HH), 256, asm_sz>>>();

    // 5. output projection -> d_out (fp32)
    gemm_f16x3<1><<<dim3(CC/128, MM/128), 256, gsm>>>(
        ah, al, wh + (size_t)3*CC*CC, wl + (size_t)3*CC*CC, bo, nullptr, nullptr,
        out, nullptr, nullptr, nullptr, nullptr, nullptr, nullptr);
}

// round 13
// speedup vs baseline: 1.0856x; 1.0856x over previous
#include <cuda_runtime.h>
#include <cuda_fp16.h>
#include <cstdint>

// B=2, T=2048, C=1024, H=16, D=64, causal MHA, fp32 in/out.
#define BB 2
#define TT 2048
#define CC 1024
#define HH 16
#define DD 64
#define MM (BB*TT)

typedef __half h16;

// ---------------- scratch (allocation-free) ----------------
__device__ h16 g_xh[MM*CC], g_xl[MM*CC];
__device__ h16 g_ah[MM*CC], g_al[MM*CC];
__device__ h16 g_wh[4*CC*CC], g_wl[4*CC*CC];   // [Wq|Wk|Wv|Wo] transposed [n][k]
__device__ h16 g_qh[BB*HH*TT*DD], g_ql[BB*HH*TT*DD];
__device__ h16 g_kh[BB*HH*TT*DD], g_kl[BB*HH*TT*DD];
__device__ h16 g_vh[BB*HH*TT*DD], g_vl[BB*HH*TT*DD];

// ---------------- helpers (sm_80-baseline PTX only) ----------------
__device__ __forceinline__ uint32_t smem_u32(const void* p) {
    return (uint32_t)__cvta_generic_to_shared(p);
}

#define CP16(dst, src) \
    asm volatile("cp.async.cg.shared.global [%0], [%1], 16;" :: "r"(dst), "l"(src) : "memory")
#define CP_COMMIT() asm volatile("cp.async.commit_group;" ::: "memory")
#define CP_WAIT(n)  asm volatile("cp.async.wait_group %0;" :: "n"(n) : "memory")

__device__ __forceinline__ void ldm4(uint32_t* r, uint32_t a) {
    asm volatile("ldmatrix.sync.aligned.m8n8.x4.shared.b16 {%0,%1,%2,%3}, [%4];"
                 : "=r"(r[0]), "=r"(r[1]), "=r"(r[2]), "=r"(r[3]) : "r"(a));
}
__device__ __forceinline__ void ldm4t(uint32_t* r, uint32_t a) {
    asm volatile("ldmatrix.sync.aligned.m8n8.x4.trans.shared.b16 {%0,%1,%2,%3}, [%4];"
                 : "=r"(r[0]), "=r"(r[1]), "=r"(r[2]), "=r"(r[3]) : "r"(a));
}
__device__ __forceinline__ void mma_f32(float* d, const uint32_t* a, const uint32_t* b) {
    asm volatile("mma.sync.aligned.m16n8k16.row.col.f32.f16.f16.f32 "
                 "{%0,%1,%2,%3}, {%4,%5,%6,%7}, {%8,%9}, {%0,%1,%2,%3};"
                 : "+f"(d[0]), "+f"(d[1]), "+f"(d[2]), "+f"(d[3])
                 : "r"(a[0]), "r"(a[1]), "r"(a[2]), "r"(a[3]), "r"(b[0]), "r"(b[1]));
}

__device__ __forceinline__ float2 h2f(uint32_t u) {
    __half2 h = *reinterpret_cast<__half2*>(&u);
    return __half22float2(h);
}
__device__ __forceinline__ uint32_t pk2h(float a, float b) {
    __half2 t = __floats2half2_rn(a, b);
    return *reinterpret_cast<uint32_t*>(&t);
}
__device__ __forceinline__ void split_st(h16* hi, h16* lo, size_t off, float a, float b) {
    uint32_t hp = pk2h(a, b);
    float2 back = h2f(hp);
    *(uint32_t*)(hi + off) = hp;
    *(uint32_t*)(lo + off) = pk2h(a - back.x, b - back.y);
}

// ---------------------------------------------------------------------------
__global__ void split_kernel(const float* __restrict__ x,
                             h16* __restrict__ hi, h16* __restrict__ lo) {
    int i = blockIdx.x * blockDim.x + threadIdx.x;
    float4 v = ((const float4*)x)[i];
    split_st(hi, lo, 4*(size_t)i,     v.x, v.y);
    split_st(hi, lo, 4*(size_t)i + 2, v.z, v.w);
}

// ---------------------------------------------------------------------------
__global__ void tsplit_kernel(const float* __restrict__ W0, const float* __restrict__ W1,
                              const float* __restrict__ W2, const float* __restrict__ W3,
                              h16* __restrict__ hi, h16* __restrict__ lo) {
    __shared__ float t[32][33];
    int tx = threadIdx.x, ty = threadIdx.y;          // (32, 8)
    int n0 = blockIdx.x * 32, k0 = blockIdx.y * 32;
    int z = blockIdx.z;
    const float* W = (z == 0) ? W0 : (z == 1) ? W1 : (z == 2) ? W2 : W3;
    h16* hz = hi + (size_t)z * CC * CC;
    h16* lz = lo + (size_t)z * CC * CC;
#pragma unroll
    for (int i = 0; i < 4; i++)
        t[ty + 8*i][tx] = W[(size_t)(k0 + ty + 8*i) * CC + n0 + tx];
    __syncthreads();
#pragma unroll
    for (int i = 0; i < 4; i++) {
        float v = t[tx][ty + 8*i];
        __half h = __float2half_rn(v);
        size_t o = (size_t)(n0 + ty + 8*i) * CC + k0 + tx;
        hz[o] = h;
        lz[o] = __float2half_rn(v - __half2float(h));
    }
}

// ---------------------------------------------------------------------------
// fp16x3 GEMM (uniform f32-acc): 128x128 tile, K-chunk 64, 2-stage cp.async.
// MODE 0: fused QKV (grid.x covers N=3072), split-fp16 out to [B,H,T,D].
// MODE 1: single GEMM (Wo), fp32 [M,N].
// ---------------------------------------------------------------------------
#define GSTG 65536
#define NKT  16

template<int MODE>
__global__ __launch_bounds__(256) void gemm_f16x3(
    const h16* __restrict__ Ah, const h16* __restrict__ Al,
    const h16* __restrict__ Bh, const h16* __restrict__ Bl,
    const float* __restrict__ bias0, const float* __restrict__ bias1,
    const float* __restrict__ bias2,
    float* __restrict__ outF,
    h16* __restrict__ o0h, h16* __restrict__ o0l,
    h16* __restrict__ o1h, h16* __restrict__ o1l,
    h16* __restrict__ o2h, h16* __restrict__ o2l)
{
    extern __shared__ char smraw[];
    const uint32_t sbase = smem_u32(smraw);

    int tid = threadIdx.x, lane = tid & 31, wid = tid >> 5;
    int wm = wid & 1, wn = wid >> 1;
    int m0 = blockIdx.y << 7, n0 = blockIdx.x << 7;

    const float* bias = bias0;
    h16 *oh = o0h, *ol = o0l;
    float scale = 1.0f;
    if (MODE == 0) {
        int sec = n0 >> 10;
        bias = (sec == 0) ? bias0 : (sec == 1) ? bias1 : bias2;
        oh   = (sec == 0) ? o0h   : (sec == 1) ? o1h   : o2h;
        ol   = (sec == 0) ? o0l   : (sec == 1) ? o1l   : o2l;
        // Q pre-scaled by (1/8)*log2(e): softmax runs in exp2 domain.
        scale = (sec == 0) ? 0.180336885f : 1.0f;
    }

    float acc[4][4][4] = {};

    auto load_stage = [&](int kt, int s) {
        uint32_t sb = sbase + (uint32_t)s * GSTG;
#pragma unroll
        for (int i = 0; i < 4; i++) {
            int id = tid + i*256;
            int r = id >> 3, c = id & 7;
            uint32_t phys = (uint32_t)(r*128 + ((c ^ (r & 7)) << 4));
            size_t ga = (size_t)(m0 + r)*CC + kt*64 + c*8;
            size_t gb = (size_t)(n0 + r)*CC + kt*64 + c*8;
            CP16(sb +         phys, Ah + ga);
            CP16(sb + 16384 + phys, Al + ga);
            CP16(sb + 32768 + phys, Bh + gb);
            CP16(sb + 49152 + phys, Bl + gb);
        }
        CP_COMMIT();
    };

    load_stage(0, 0);

    int ahalf = lane >> 4;
    int bhalf = (lane >> 3) & 1;
    int arow = wm*64 + (lane & 15);
    int brow = wn*32 + ((lane >> 4) << 3) + (lane & 7);

    for (int kt = 0; kt < NKT; kt++) {
        if (kt + 1 < NKT) { load_stage(kt + 1, (kt + 1) & 1); CP_WAIT(1); }
        else              { CP_WAIT(0); }
        __syncthreads();

        uint32_t sb = sbase + (uint32_t)(kt & 1) * GSTG;
#pragma unroll
        for (int kk = 0; kk < 4; kk++) {
            uint32_t aswz = (uint32_t)(((2*kk + ahalf) ^ (arow & 7)) << 4);
            uint32_t bswz = (uint32_t)(((2*kk + bhalf) ^ (brow & 7)) << 4);
            uint32_t ah4[4][4], al4[4][4], bh4[2][4], bl4[2][4];
#pragma unroll
            for (int mf = 0; mf < 4; mf++) {
                uint32_t off = (uint32_t)((arow + mf*16) * 128) + aswz;
                ldm4(ah4[mf], sb + off);
                ldm4(al4[mf], sb + 16384 + off);
            }
#pragma unroll
            for (int nh = 0; nh < 2; nh++) {
                uint32_t off = (uint32_t)((brow + nh*16) * 128) + bswz;
                ldm4(bh4[nh], sb + 32768 + off);
                ldm4(bl4[nh], sb + 49152 + off);
            }
#pragma unroll
            for (int mf = 0; mf < 4; mf++)
#pragma unroll
                for (int nf = 0; nf < 4; nf++) {
                    const uint32_t* ph = bh4[nf >> 1] + (nf & 1)*2;
                    const uint32_t* pl = bl4[nf >> 1] + (nf & 1)*2;
                    mma_f32(acc[mf][nf], ah4[mf], ph);
                    mma_f32(acc[mf][nf], ah4[mf], pl);
                    mma_f32(acc[mf][nf], al4[mf], ph);
                }
        }
        __syncthreads();
    }

    int g = lane >> 2, t2 = (lane & 3) * 2;
#pragma unroll
    for (int nf = 0; nf < 4; nf++) {
        int col = n0 + wn*32 + nf*8 + t2;
        int lc = col & (CC - 1);
        float2 bb = *(const float2*)(bias + lc);
#pragma unroll
        for (int mf = 0; mf < 4; mf++) {
            int m1 = m0 + wm*64 + mf*16 + g;
            float v0 = acc[mf][nf][0] + bb.x, v1 = acc[mf][nf][1] + bb.y;
            float v2 = acc[mf][nf][2] + bb.x, v3 = acc[mf][nf][3] + bb.y;
            if (MODE == 0) {
                int h = lc >> 6, d = lc & 63;
                int b1 = m1 >> 11, t1 = m1 & (TT - 1);
                size_t base = ((size_t)(b1*HH + h)*TT) * DD + d;
                split_st(oh, ol, base + (size_t)t1*DD,       v0*scale, v1*scale);
                split_st(oh, ol, base + (size_t)(t1 + 8)*DD, v2*scale, v3*scale);
            } else {
                *(float2*)(outF + (size_t)m1*CC + col)       = make_float2(v0, v1);
                *(float2*)(outF + (size_t)(m1 + 8)*CC + col) = make_float2(v2, v3);
            }
        }
    }
}

// ---------------------------------------------------------------------------
// Tensor-core causal flash attention, fp16x3, f32 accumulate, exp2 domain.
// R11 structure exactly (no pruning guards): q-tile 128, k-tile 128,
// Q frags resident, occ-1. smem: Qh/Ql(32K) + 2 x 64K KV stages = 160KB.
// ---------------------------------------------------------------------------
__global__ __launch_bounds__(256) void attn_mma()
{
    extern __shared__ char smraw[];
    const uint32_t sb = smem_u32(smraw);
    const uint32_t QH = 0, QL = 16384, ST = 32768, STSZ = 65536;

    int tid = threadIdx.x, lane = tid & 31, w = tid >> 5;
    int bh = blockIdx.y;
    int qt = (int)gridDim.x - 1 - (int)blockIdx.x;   // heavy tiles first
    int q0 = qt * 128;
    int nkt = qt + 1;

    const h16* Qh = g_qh + (size_t)bh*TT*DD;
    const h16* Ql = g_ql + (size_t)bh*TT*DD;
    const h16* Kh = g_kh + (size_t)bh*TT*DD;
    const h16* Kl = g_kl + (size_t)bh*TT*DD;
    const h16* Vh = g_vh + (size_t)bh*TT*DD;
    const h16* Vl = g_vl + (size_t)bh*TT*DD;

    auto load_kv = [&](int kt, int s) {
        uint32_t base = sb + ST + (uint32_t)s * STSZ;
        int k0 = kt * 128;
#pragma unroll
        for (int i = 0; i < 4; i++) {
            int id = tid + i*256;
            int r = id >> 3, c = id & 7;
            uint32_t phys = (uint32_t)(r*128 + ((c ^ (r & 7)) << 4));
            size_t gsrc = (size_t)(k0 + r)*DD + c*8;
            CP16(base +         phys, Kh + gsrc);
            CP16(base + 16384 + phys, Kl + gsrc);
            CP16(base + 32768 + phys, Vh + gsrc);
            CP16(base + 49152 + phys, Vl + gsrc);
        }
        CP_COMMIT();
    };

    // Q tile (128 x 64) hi/lo
#pragma unroll
    for (int m = 0; m < 2; m++)
#pragma unroll
        for (int i = 0; i < 4; i++) {
            int id = tid + i*256;
            int r = id >> 3, c = id & 7;
            uint32_t dst = sb + (m ? QL : QH) + (uint32_t)(r*128 + ((c ^ (r & 7)) << 4));
            const h16* src = (m ? Ql : Qh) + (size_t)(q0 + r)*DD + c*8;
            CP16(dst, src);
        }
    CP_COMMIT();
    load_kv(0, 0);

    CP_WAIT(1);
    __syncthreads();

    // Q fragments (resident)
    uint32_t qfh[4][4], qfl[4][4];
    int arow = w*16 + (lane & 15), ahalf = lane >> 4;
#pragma unroll
    for (int kk = 0; kk < 4; kk++) {
        uint32_t off = (uint32_t)(arow*128 + (((2*kk + ahalf) ^ (arow & 7)) << 4));
        ldm4(qfh[kk], sb + QH + off);
        ldm4(qfl[kk], sb + QL + off);
    }

    float oacc[8][4] = {};
    float mrow0 = -1e30f, mrow1 = -1e30f;
    float lsum0 = 0.f, lsum1 = 0.f;

    int g = lane >> 2, t2 = (lane & 3) * 2;
    int r0g = q0 + 16*w + g, r1g = r0g + 8;
    int bhalf = (lane >> 3) & 1;
    int vi = lane >> 3, vr = lane & 7;

    for (int kt = 0; kt < nkt; kt++) {
        if (kt + 1 < nkt) { load_kv(kt + 1, (kt + 1) & 1); CP_WAIT(1); }
        else              { CP_WAIT(0); }
        __syncthreads();

        int k0 = kt * 128;
        uint32_t st = sb + ST + (uint32_t)(kt & 1) * STSZ;

        // ---- S = Q K^T over 128 keys ----
        float sacc[16][4] = {};
#pragma unroll
        for (int kk = 0; kk < 4; kk++) {
#pragma unroll
            for (int ng = 0; ng < 8; ng++) {
                int brow = ng*16 + ((lane >> 4) << 3) + (lane & 7);
                uint32_t off = (uint32_t)(brow*128 + (((2*kk + bhalf) ^ (brow & 7)) << 4));
                uint32_t kh4[4], kl4[4];
                ldm4(kh4, st + off);
                ldm4(kl4, st + 16384 + off);
                mma_f32(sacc[2*ng],   qfh[kk], kh4);
                mma_f32(sacc[2*ng],   qfh[kk], kl4);
                mma_f32(sacc[2*ng],   qfl[kk], kh4);
                mma_f32(sacc[2*ng+1], qfh[kk], kh4 + 2);
                mma_f32(sacc[2*ng+1], qfh[kk], kl4 + 2);
                mma_f32(sacc[2*ng+1], qfl[kk], kh4 + 2);
            }
        }

        // ---- causal mask ----
        if (k0 + 127 > r0g) {
#pragma unroll
            for (int j = 0; j < 16; j++) {
                int col = k0 + 8*j + t2;
                if (col     > r0g) sacc[j][0] = -1e30f;
                if (col + 1 > r0g) sacc[j][1] = -1e30f;
                if (col     > r1g) sacc[j][2] = -1e30f;
                if (col + 1 > r1g) sacc[j][3] = -1e30f;
            }
        }

        // ---- online softmax (exp2 domain) ----
        float tm0 = -1e30f, tm1 = -1e30f;
#pragma unroll
        for (int j = 0; j < 16; j++) {
            tm0 = fmaxf(tm0, fmaxf(sacc[j][0], sacc[j][1]));
            tm1 = fmaxf(tm1, fmaxf(sacc[j][2], sacc[j][3]));
        }
        tm0 = fmaxf(tm0, __shfl_xor_sync(0xffffffffu, tm0, 1));
        tm0 = fmaxf(tm0, __shfl_xor_sync(0xffffffffu, tm0, 2));
        tm1 = fmaxf(tm1, __shfl_xor_sync(0xffffffffu, tm1, 1));
        tm1 = fmaxf(tm1, __shfl_xor_sync(0xffffffffu, tm1, 2));
        float mn0 = fmaxf(mrow0, tm0), mn1 = fmaxf(mrow1, tm1);
        float c0 = exp2f(mrow0 - mn0), c1 = exp2f(mrow1 - mn1);
        mrow0 = mn0; mrow1 = mn1;

        float ps0 = 0.f, ps1 = 0.f;
        uint32_t pfh[8][4], pfl[8][4];
#pragma unroll
        for (int kc = 0; kc < 8; kc++) {
#pragma unroll
            for (int jj = 0; jj < 2; jj++) {
                int j = 2*kc + jj;
                float p0 = exp2f(sacc[j][0] - mn0);
                float p1 = exp2f(sacc[j][1] - mn0);
                float p2 = exp2f(sacc[j][2] - mn1);
                float p3 = exp2f(sacc[j][3] - mn1);
                ps0 += p0 + p1; ps1 += p2 + p3;
                uint32_t hp01 = pk2h(p0, p1);
                uint32_t hp23 = pk2h(p2, p3);
                float2 b01 = h2f(hp01), b23 = h2f(hp23);
                pfh[kc][2*jj]   = hp01;
                pfh[kc][2*jj+1] = hp23;
                pfl[kc][2*jj]   = pk2h(p0 - b01.x, p1 - b01.y);
                pfl[kc][2*jj+1] = pk2h(p2 - b23.x, p3 - b23.y);
            }
        }
        lsum0 = lsum0 * c0 + ps0;
        lsum1 = lsum1 * c1 + ps1;
#pragma unroll
        for (int j = 0; j < 8; j++) {
            oacc[j][0] *= c0; oacc[j][1] *= c0;
            oacc[j][2] *= c1; oacc[j][3] *= c1;
        }

        // ---- O += P V over 128 keys ----
#pragma unroll
        for (int kc = 0; kc < 8; kc++) {
#pragma unroll
            for (int dg = 0; dg < 4; dg++) {
                int key = kc*16 + 8*(vi & 1) + vr;
                int dc = 2*dg + (vi >> 1);
                uint32_t off = (uint32_t)(key*128 + ((dc ^ (key & 7)) << 4));
                uint32_t vh4[4], vl4[4];
                ldm4t(vh4, st + 32768 + off);
                ldm4t(vl4, st + 49152 + off);
                mma_f32(oacc[2*dg],   pfh[kc], vh4);
                mma_f32(oacc[2*dg],   pfh[kc], vl4);
                mma_f32(oacc[2*dg],   pfl[kc], vh4);
                mma_f32(oacc[2*dg+1], pfh[kc], vh4 + 2);
                mma_f32(oacc[2*dg+1], pfh[kc], vl4 + 2);
                mma_f32(oacc[2*dg+1], pfl[kc], vh4 + 2);
            }
        }
        __syncthreads();
    }

    lsum0 += __shfl_xor_sync(0xffffffffu, lsum0, 1);
    lsum0 += __shfl_xor_sync(0xffffffffu, lsum0, 2);
    lsum1 += __shfl_xor_sync(0xffffffffu, lsum1, 1);
    lsum1 += __shfl_xor_sync(0xffffffffu, lsum1, 2);
    float inv0 = 1.f / lsum0, inv1 = 1.f / lsum1;

    int b = bh >> 4, h = bh & 15;
    size_t row0 = (size_t)(b*TT + r0g) * CC + h*DD;
    size_t row1 = (size_t)(b*TT + r1g) * CC + h*DD;
#pragma unroll
    for (int j = 0; j < 8; j++) {
        int d = 8*j + t2;
        split_st(g_ah, g_al, row0 + d, oacc[j][0]*inv0, oacc[j][1]*inv0);
        split_st(g_ah, g_al, row1 + d, oacc[j][2]*inv1, oacc[j][3]*inv1);
    }
}

// ---------------------------------------------------------------------------
extern "C" void kernel_launch(void* const* d_in, const int* in_sizes, int n_in,
                              void* d_out, int out_size)
{
    (void)in_sizes; (void)n_in; (void)out_size;
    const float* x  = (const float*)d_in[0];
    const float* Wq = (const float*)d_in[1];
    const float* bq = (const float*)d_in[2];
    const float* Wk = (const float*)d_in[3];
    const float* bk = (const float*)d_in[4];
    const float* Wv = (const float*)d_in[5];
    const float* bv = (const float*)d_in[6];
    const float* Wo = (const float*)d_in[7];
    const float* bo = (const float*)d_in[8];
    float* out = (float*)d_out;

    h16 *xh, *xl, *ah, *al, *wh, *wl, *qh, *ql, *kh, *kl, *vh, *vl;
    cudaGetSymbolAddress((void**)&xh, g_xh);
    cudaGetSymbolAddress((void**)&xl, g_xl);
    cudaGetSymbolAddress((void**)&ah, g_ah);
    cudaGetSymbolAddress((void**)&al, g_al);
    cudaGetSymbolAddress((void**)&wh, g_wh);
    cudaGetSymbolAddress((void**)&wl, g_wl);
    cudaGetSymbolAddress((void**)&qh, g_qh);
    cudaGetSymbolAddress((void**)&ql, g_ql);
    cudaGetSymbolAddress((void**)&kh, g_kh);
    cudaGetSymbolAddress((void**)&kl, g_kl);
    cudaGetSymbolAddress((void**)&vh, g_vh);
    cudaGetSymbolAddress((void**)&vl, g_vl);

    // 1. split x
    split_kernel<<<(MM*CC/4)/256, 256>>>(x, xh, xl);

    // 2. transpose+split all 4 weights (one launch)
    tsplit_kernel<<<dim3(CC/32, CC/32, 4), dim3(32, 8)>>>(Wq, Wk, Wv, Wo, wh, wl);

    // 3. fused QKV projection (N=3072); Q pre-scaled by log2e/8 (exp2 domain)
    const int gsm = 2 * GSTG;  // 128 KB
    cudaFuncSetAttribute(gemm_f16x3<0>, cudaFuncAttributeMaxDynamicSharedMemorySize, gsm);
    cudaFuncSetAttribute(gemm_f16x3<1>, cudaFuncAttributeMaxDynamicSharedMemorySize, gsm);
    gemm_f16x3<0><<<dim3(3*CC/128, MM/128), 256, gsm>>>(
        xh, xl, wh, wl, bq, bk, bv,
        nullptr, qh, ql, kh, kl, vh, vl);

    // 4. tensor-core flash attention (k-tile 128, exp2 domain)
    const int asm_sz = 32768 + 2*65536;   // 163840
    cudaFuncSetAttribute(attn_mma, cudaFuncAttributeMaxDynamicSharedMemorySize, asm_sz);
    attn_mma<<<dim3(TT/128, BB*HH), 256, asm_sz>>>();

    // 5. output projection -> d_out (fp32)
    gemm_f16x3<1><<<dim3(CC/128, MM/128), 256, gsm>>>(
        ah, al, wh + (size_t)3*CC*CC, wl + (size_t)3*CC*CC, bo, nullptr, nullptr,
        out, nullptr, nullptr, nullptr, nullptr, nullptr, nullptr);
}

// round 14
// speedup vs baseline: 1.0870x; 1.0013x over previous
#include <cuda_runtime.h>
#include <cuda_fp16.h>
#include <cstdint>

// B=2, T=2048, C=1024, H=16, D=64, causal MHA, fp32 in/out.
#define BB 2
#define TT 2048
#define CC 1024
#define HH 16
#define DD 64
#define MM (BB*TT)

typedef __half h16;

// ---------------- scratch (allocation-free) ----------------
__device__ h16 g_xh[MM*CC], g_xl[MM*CC];
__device__ h16 g_ah[MM*CC], g_al[MM*CC];
__device__ h16 g_wh[4*CC*CC], g_wl[4*CC*CC];   // [Wq|Wk|Wv|Wo] transposed [n][k]
__device__ h16 g_qh[BB*HH*TT*DD], g_ql[BB*HH*TT*DD];
__device__ h16 g_kh[BB*HH*TT*DD], g_kl[BB*HH*TT*DD];
__device__ h16 g_vh[BB*HH*TT*DD], g_vl[BB*HH*TT*DD];

// ---------------- helpers (sm_80-baseline PTX only) ----------------
__device__ __forceinline__ uint32_t smem_u32(const void* p) {
    return (uint32_t)__cvta_generic_to_shared(p);
}

#define CP16(dst, src) \
    asm volatile("cp.async.cg.shared.global [%0], [%1], 16;" :: "r"(dst), "l"(src) : "memory")
#define CP_COMMIT() asm volatile("cp.async.commit_group;" ::: "memory")
#define CP_WAIT(n)  asm volatile("cp.async.wait_group %0;" :: "n"(n) : "memory")

__device__ __forceinline__ void ldm4(uint32_t* r, uint32_t a) {
    asm volatile("ldmatrix.sync.aligned.m8n8.x4.shared.b16 {%0,%1,%2,%3}, [%4];"
                 : "=r"(r[0]), "=r"(r[1]), "=r"(r[2]), "=r"(r[3]) : "r"(a));
}
__device__ __forceinline__ void ldm4t(uint32_t* r, uint32_t a) {
    asm volatile("ldmatrix.sync.aligned.m8n8.x4.trans.shared.b16 {%0,%1,%2,%3}, [%4];"
                 : "=r"(r[0]), "=r"(r[1]), "=r"(r[2]), "=r"(r[3]) : "r"(a));
}
__device__ __forceinline__ void mma_f32(float* d, const uint32_t* a, const uint32_t* b) {
    asm volatile("mma.sync.aligned.m16n8k16.row.col.f32.f16.f16.f32 "
                 "{%0,%1,%2,%3}, {%4,%5,%6,%7}, {%8,%9}, {%0,%1,%2,%3};"
                 : "+f"(d[0]), "+f"(d[1]), "+f"(d[2]), "+f"(d[3])
                 : "r"(a[0]), "r"(a[1]), "r"(a[2]), "r"(a[3]), "r"(b[0]), "r"(b[1]));
}

__device__ __forceinline__ float2 h2f(uint32_t u) {
    __half2 h = *reinterpret_cast<__half2*>(&u);
    return __half22float2(h);
}
__device__ __forceinline__ uint32_t pk2h(float a, float b) {
    __half2 t = __floats2half2_rn(a, b);
    return *reinterpret_cast<uint32_t*>(&t);
}
__device__ __forceinline__ void split_st(h16* hi, h16* lo, size_t off, float a, float b) {
    uint32_t hp = pk2h(a, b);
    float2 back = h2f(hp);
    *(uint32_t*)(hi + off) = hp;
    *(uint32_t*)(lo + off) = pk2h(a - back.x, b - back.y);
}

// ---------------------------------------------------------------------------
__global__ void split_kernel(const float* __restrict__ x,
                             h16* __restrict__ hi, h16* __restrict__ lo) {
    int i = blockIdx.x * blockDim.x + threadIdx.x;
    float4 v = ((const float4*)x)[i];
    split_st(hi, lo, 4*(size_t)i,     v.x, v.y);
    split_st(hi, lo, 4*(size_t)i + 2, v.z, v.w);
}

// ---------------------------------------------------------------------------
__global__ void tsplit_kernel(const float* __restrict__ W0, const float* __restrict__ W1,
                              const float* __restrict__ W2, const float* __restrict__ W3,
                              h16* __restrict__ hi, h16* __restrict__ lo) {
    __shared__ float t[32][33];
    int tx = threadIdx.x, ty = threadIdx.y;          // (32, 8)
    int n0 = blockIdx.x * 32, k0 = blockIdx.y * 32;
    int z = blockIdx.z;
    const float* W = (z == 0) ? W0 : (z == 1) ? W1 : (z == 2) ? W2 : W3;
    h16* hz = hi + (size_t)z * CC * CC;
    h16* lz = lo + (size_t)z * CC * CC;
#pragma unroll
    for (int i = 0; i < 4; i++)
        t[ty + 8*i][tx] = W[(size_t)(k0 + ty + 8*i) * CC + n0 + tx];
    __syncthreads();
#pragma unroll
    for (int i = 0; i < 4; i++) {
        float v = t[tx][ty + 8*i];
        __half h = __float2half_rn(v);
        size_t o = (size_t)(n0 + ty + 8*i) * CC + k0 + tx;
        hz[o] = h;
        lz[o] = __float2half_rn(v - __half2float(h));
    }
}

// ---------------------------------------------------------------------------
// fp16x3 GEMM (uniform f32-acc): 128x128 tile, K-chunk 64, 2-stage cp.async.
// MODE 0: fused QKV (grid.x covers N=3072), split-fp16 out to [B,H,T,D].
// MODE 1: single GEMM (Wo), fp32 [M,N].
// ---------------------------------------------------------------------------
#define GSTG 65536
#define NKT  16

template<int MODE>
__global__ __launch_bounds__(256) void gemm_f16x3(
    const h16* __restrict__ Ah, const h16* __restrict__ Al,
    const h16* __restrict__ Bh, const h16* __restrict__ Bl,
    const float* __restrict__ bias0, const float* __restrict__ bias1,
    const float* __restrict__ bias2,
    float* __restrict__ outF,
    h16* __restrict__ o0h, h16* __restrict__ o0l,
    h16* __restrict__ o1h, h16* __restrict__ o1l,
    h16* __restrict__ o2h, h16* __restrict__ o2l)
{
    extern __shared__ char smraw[];
    const uint32_t sbase = smem_u32(smraw);

    int tid = threadIdx.x, lane = tid & 31, wid = tid >> 5;
    int wm = wid & 1, wn = wid >> 1;
    int m0 = blockIdx.y << 7, n0 = blockIdx.x << 7;

    const float* bias = bias0;
    h16 *oh = o0h, *ol = o0l;
    float scale = 1.0f;
    if (MODE == 0) {
        int sec = n0 >> 10;
        bias = (sec == 0) ? bias0 : (sec == 1) ? bias1 : bias2;
        oh   = (sec == 0) ? o0h   : (sec == 1) ? o1h   : o2h;
        ol   = (sec == 0) ? o0l   : (sec == 1) ? o1l   : o2l;
        // Q pre-scaled by (1/8)*log2(e): softmax runs in exp2 domain.
        scale = (sec == 0) ? 0.180336885f : 1.0f;
    }

    float acc[4][4][4] = {};

    auto load_stage = [&](int kt, int s) {
        uint32_t sb = sbase + (uint32_t)s * GSTG;
#pragma unroll
        for (int i = 0; i < 4; i++) {
            int id = tid + i*256;
            int r = id >> 3, c = id & 7;
            uint32_t phys = (uint32_t)(r*128 + ((c ^ (r & 7)) << 4));
            size_t ga = (size_t)(m0 + r)*CC + kt*64 + c*8;
            size_t gb = (size_t)(n0 + r)*CC + kt*64 + c*8;
            CP16(sb +         phys, Ah + ga);
            CP16(sb + 16384 + phys, Al + ga);
            CP16(sb + 32768 + phys, Bh + gb);
            CP16(sb + 49152 + phys, Bl + gb);
        }
        CP_COMMIT();
    };

    load_stage(0, 0);

    int ahalf = lane >> 4;
    int bhalf = (lane >> 3) & 1;
    int arow = wm*64 + (lane & 15);
    int brow = wn*32 + ((lane >> 4) << 3) + (lane & 7);

    for (int kt = 0; kt < NKT; kt++) {
        if (kt + 1 < NKT) { load_stage(kt + 1, (kt + 1) & 1); CP_WAIT(1); }
        else              { CP_WAIT(0); }
        __syncthreads();

        uint32_t sb = sbase + (uint32_t)(kt & 1) * GSTG;
#pragma unroll
        for (int kk = 0; kk < 4; kk++) {
            uint32_t aswz = (uint32_t)(((2*kk + ahalf) ^ (arow & 7)) << 4);
            uint32_t bswz = (uint32_t)(((2*kk + bhalf) ^ (brow & 7)) << 4);
            uint32_t ah4[4][4], al4[4][4], bh4[2][4], bl4[2][4];
#pragma unroll
            for (int mf = 0; mf < 4; mf++) {
                uint32_t off = (uint32_t)((arow + mf*16) * 128) + aswz;
                ldm4(ah4[mf], sb + off);
                ldm4(al4[mf], sb + 16384 + off);
            }
#pragma unroll
            for (int nh = 0; nh < 2; nh++) {
                uint32_t off = (uint32_t)((brow + nh*16) * 128) + bswz;
                ldm4(bh4[nh], sb + 32768 + off);
                ldm4(bl4[nh], sb + 49152 + off);
            }
#pragma unroll
            for (int mf = 0; mf < 4; mf++)
#pragma unroll
                for (int nf = 0; nf < 4; nf++) {
                    const uint32_t* ph = bh4[nf >> 1] + (nf & 1)*2;
                    const uint32_t* pl = bl4[nf >> 1] + (nf & 1)*2;
                    mma_f32(acc[mf][nf], ah4[mf], ph);
                    mma_f32(acc[mf][nf], ah4[mf], pl);
                    mma_f32(acc[mf][nf], al4[mf], ph);
                }
        }
        __syncthreads();
    }

    int g = lane >> 2, t2 = (lane & 3) * 2;
#pragma unroll
    for (int nf = 0; nf < 4; nf++) {
        int col = n0 + wn*32 + nf*8 + t2;
        int lc = col & (CC - 1);
        float2 bb = *(const float2*)(bias + lc);
#pragma unroll
        for (int mf = 0; mf < 4; mf++) {
            int m1 = m0 + wm*64 + mf*16 + g;
            float v0 = acc[mf][nf][0] + bb.x, v1 = acc[mf][nf][1] + bb.y;
            float v2 = acc[mf][nf][2] + bb.x, v3 = acc[mf][nf][3] + bb.y;
            if (MODE == 0) {
                int h = lc >> 6, d = lc & 63;
                int b1 = m1 >> 11, t1 = m1 & (TT - 1);
                size_t base = ((size_t)(b1*HH + h)*TT) * DD + d;
                split_st(oh, ol, base + (size_t)t1*DD,       v0*scale, v1*scale);
                split_st(oh, ol, base + (size_t)(t1 + 8)*DD, v2*scale, v3*scale);
            } else {
                *(float2*)(outF + (size_t)m1*CC + col)       = make_float2(v0, v1);
                *(float2*)(outF + (size_t)(m1 + 8)*CC + col) = make_float2(v2, v3);
            }
        }
    }
}

// ---------------------------------------------------------------------------
// Tensor-core causal flash attention, fp16x3, f32 accumulate, exp2 domain.
// 4m x 2n warp layout: warp (wm, wn) owns 32 q-rows x 64 keys.
// K/V LDSM per warp halved vs 8x1; per-tile cross-warp MAX exchange via smem;
// lsum + O merged across n-halves ONCE at the end (stage-0 smem reuse).
// q-tile 128, k-tile 128, 2-stage KV. smem = 32K Q + 2x64K KV + 1K exch.
// ---------------------------------------------------------------------------
__global__ __launch_bounds__(256) void attn_mma()
{
    extern __shared__ char smraw[];
    const uint32_t sb = smem_u32(smraw);
    const uint32_t QH = 0, QL = 16384, ST = 32768, STSZ = 65536;
    float* sExc = (float*)(smraw + ST + 2*STSZ);    // float[2][128]

    int tid = threadIdx.x, lane = tid & 31, w = tid >> 5;
    int wm = w & 3, wn = w >> 2;
    int bh = blockIdx.y;
    int qt = (int)gridDim.x - 1 - (int)blockIdx.x;   // heavy tiles first
    int q0 = qt * 128;
    int nkt = qt + 1;

    const h16* Qh = g_qh + (size_t)bh*TT*DD;
    const h16* Ql = g_ql + (size_t)bh*TT*DD;
    const h16* Kh = g_kh + (size_t)bh*TT*DD;
    const h16* Kl = g_kl + (size_t)bh*TT*DD;
    const h16* Vh = g_vh + (size_t)bh*TT*DD;
    const h16* Vl = g_vl + (size_t)bh*TT*DD;

    auto load_kv = [&](int kt, int s) {
        uint32_t base = sb + ST + (uint32_t)s * STSZ;
        int k0 = kt * 128;
#pragma unroll
        for (int i = 0; i < 4; i++) {
            int id = tid + i*256;
            int r = id >> 3, c = id & 7;
            uint32_t phys = (uint32_t)(r*128 + ((c ^ (r & 7)) << 4));
            size_t gsrc = (size_t)(k0 + r)*DD + c*8;
            CP16(base +         phys, Kh + gsrc);
            CP16(base + 16384 + phys, Kl + gsrc);
            CP16(base + 32768 + phys, Vh + gsrc);
            CP16(base + 49152 + phys, Vl + gsrc);
        }
        CP_COMMIT();
    };

    // Q tile (128 x 64) hi/lo
#pragma unroll
    for (int m = 0; m < 2; m++)
#pragma unroll
        for (int i = 0; i < 4; i++) {
            int id = tid + i*256;
            int r = id >> 3, c = id & 7;
            uint32_t dst = sb + (m ? QL : QH) + (uint32_t)(r*128 + ((c ^ (r & 7)) << 4));
            const h16* src = (m ? Ql : Qh) + (size_t)(q0 + r)*DD + c*8;
            CP16(dst, src);
        }
    CP_COMMIT();
    load_kv(0, 0);

    CP_WAIT(1);
    __syncthreads();

    float oacc[2][8][4] = {};
    float mrow[2][2] = {{-1e30f, -1e30f}, {-1e30f, -1e30f}};
    float lsum[2][2] = {};

    int g = lane >> 2, t2 = (lane & 3) * 2;
    int ahalf = lane >> 4;
    int bhalf = (lane >> 3) & 1;
    int vi = lane >> 3, vr = lane & 7;

    for (int kt = 0; kt < nkt; kt++) {
        if (kt + 1 < nkt) { load_kv(kt + 1, (kt + 1) & 1); CP_WAIT(1); }
        else              { CP_WAIT(0); }
        __syncthreads();

        int k0 = kt * 128;
        uint32_t st = sb + ST + (uint32_t)(kt & 1) * STSZ;

        // ---- S = Q K^T : rows wm*32 + mf*16, keys wn*64 + ng*16 ----
        float sacc[2][8][4] = {};
#pragma unroll
        for (int kk = 0; kk < 4; kk++) {
            uint32_t qh4[2][4], ql4[2][4];
#pragma unroll
            for (int mf = 0; mf < 2; mf++) {
                int ar = wm*32 + mf*16 + (lane & 15);
                uint32_t off = (uint32_t)(ar*128 + (((2*kk + ahalf) ^ (ar & 7)) << 4));
                ldm4(qh4[mf], sb + QH + off);
                ldm4(ql4[mf], sb + QL + off);
            }
#pragma unroll
            for (int ng = 0; ng < 4; ng++) {
                int br = wn*64 + ng*16 + ((lane >> 4) << 3) + (lane & 7);
                uint32_t off = (uint32_t)(br*128 + (((2*kk + bhalf) ^ (br & 7)) << 4));
                uint32_t kh4[4], kl4[4];
                ldm4(kh4, st + off);
                ldm4(kl4, st + 16384 + off);
#pragma unroll
                for (int mf = 0; mf < 2; mf++) {
                    mma_f32(sacc[mf][2*ng],   qh4[mf], kh4);
                    mma_f32(sacc[mf][2*ng],   qh4[mf], kl4);
                    mma_f32(sacc[mf][2*ng],   ql4[mf], kh4);
                    mma_f32(sacc[mf][2*ng+1], qh4[mf], kh4 + 2);
                    mma_f32(sacc[mf][2*ng+1], qh4[mf], kl4 + 2);
                    mma_f32(sacc[mf][2*ng+1], ql4[mf], kh4 + 2);
                }
            }
        }

        // ---- causal mask (diagonal tile only) ----
        if (kt == nkt - 1) {
#pragma unroll
            for (int mf = 0; mf < 2; mf++) {
                int r0 = q0 + wm*32 + mf*16 + g, r1 = r0 + 8;
#pragma unroll
                for (int j = 0; j < 8; j++) {
                    int col = k0 + wn*64 + 8*j + t2;
                    if (col     > r0) sacc[mf][j][0] = -1e30f;
                    if (col + 1 > r0) sacc[mf][j][1] = -1e30f;
                    if (col     > r1) sacc[mf][j][2] = -1e30f;
                    if (col + 1 > r1) sacc[mf][j][3] = -1e30f;
                }
            }
        }

        // ---- warp-local max ----
        float tm[2][2] = {{-1e30f, -1e30f}, {-1e30f, -1e30f}};
#pragma unroll
        for (int mf = 0; mf < 2; mf++)
#pragma unroll
            for (int j = 0; j < 8; j++) {
                tm[mf][0] = fmaxf(tm[mf][0], fmaxf(sacc[mf][j][0], sacc[mf][j][1]));
                tm[mf][1] = fmaxf(tm[mf][1], fmaxf(sacc[mf][j][2], sacc[mf][j][3]));
            }
#pragma unroll
        for (int mf = 0; mf < 2; mf++)
#pragma unroll
            for (int i = 0; i < 2; i++) {
                tm[mf][i] = fmaxf(tm[mf][i], __shfl_xor_sync(0xffffffffu, tm[mf][i], 1));
                tm[mf][i] = fmaxf(tm[mf][i], __shfl_xor_sync(0xffffffffu, tm[mf][i], 2));
            }

        // ---- cross-warp max exchange ----
        if ((lane & 3) == 0) {
            sExc[wn*128 + wm*32 + g]           = tm[0][0];
            sExc[wn*128 + wm*32 + g + 8]       = tm[0][1];
            sExc[wn*128 + wm*32 + 16 + g]      = tm[1][0];
            sExc[wn*128 + wm*32 + 16 + g + 8]  = tm[1][1];
        }
        __syncthreads();
        float c[2][2];
#pragma unroll
        for (int mf = 0; mf < 2; mf++)
#pragma unroll
            for (int i = 0; i < 2; i++) {
                float peer = sExc[(1 - wn)*128 + wm*32 + mf*16 + i*8 + g];
                float m2 = fmaxf(mrow[mf][i], fmaxf(tm[mf][i], peer));
                c[mf][i] = exp2f(mrow[mf][i] - m2);
                mrow[mf][i] = m2;
            }

        // ---- exp2 + pack + partial sums ----
        float ps[2][2] = {};
        uint32_t pfh[2][4][4], pfl[2][4][4];
#pragma unroll
        for (int mf = 0; mf < 2; mf++)
#pragma unroll
            for (int kc = 0; kc < 4; kc++)
#pragma unroll
                for (int jj = 0; jj < 2; jj++) {
                    int j = 2*kc + jj;
                    float p0 = exp2f(sacc[mf][j][0] - mrow[mf][0]);
                    float p1 = exp2f(sacc[mf][j][1] - mrow[mf][0]);
                    float p2 = exp2f(sacc[mf][j][2] - mrow[mf][1]);
                    float p3 = exp2f(sacc[mf][j][3] - mrow[mf][1]);
                    ps[mf][0] += p0 + p1; ps[mf][1] += p2 + p3;
                    uint32_t hp01 = pk2h(p0, p1), hp23 = pk2h(p2, p3);
                    float2 b01 = h2f(hp01), b23 = h2f(hp23);
                    pfh[mf][kc][2*jj]   = hp01;
                    pfh[mf][kc][2*jj+1] = hp23;
                    pfl[mf][kc][2*jj]   = pk2h(p0 - b01.x, p1 - b01.y);
                    pfl[mf][kc][2*jj+1] = pk2h(p2 - b23.x, p3 - b23.y);
                }
#pragma unroll
        for (int mf = 0; mf < 2; mf++) {
            lsum[mf][0] = lsum[mf][0]*c[mf][0] + ps[mf][0];
            lsum[mf][1] = lsum[mf][1]*c[mf][1] + ps[mf][1];
#pragma unroll
            for (int j = 0; j < 8; j++) {
                oacc[mf][j][0] *= c[mf][0]; oacc[mf][j][1] *= c[mf][0];
                oacc[mf][j][2] *= c[mf][1]; oacc[mf][j][3] *= c[mf][1];
            }
        }

        // ---- O += P V over this warp's 64 keys ----
#pragma unroll
        for (int kc = 0; kc < 4; kc++)
#pragma unroll
            for (int dg = 0; dg < 4; dg++) {
                int key = wn*64 + kc*16 + 8*(vi & 1) + vr;
                int dc = 2*dg + (vi >> 1);
                uint32_t off = (uint32_t)(key*128 + ((dc ^ (key & 7)) << 4));
                uint32_t vh4[4], vl4[4];
                ldm4t(vh4, st + 32768 + off);
                ldm4t(vl4, st + 49152 + off);
#pragma unroll
                for (int mf = 0; mf < 2; mf++) {
                    mma_f32(oacc[mf][2*dg],   pfh[mf][kc], vh4);
                    mma_f32(oacc[mf][2*dg],   pfh[mf][kc], vl4);
                    mma_f32(oacc[mf][2*dg],   pfl[mf][kc], vh4);
                    mma_f32(oacc[mf][2*dg+1], pfh[mf][kc], vh4 + 2);
                    mma_f32(oacc[mf][2*dg+1], pfh[mf][kc], vl4 + 2);
                    mma_f32(oacc[mf][2*dg+1], pfl[mf][kc], vh4 + 2);
                }
            }
        __syncthreads();
    }

    // ---- lsum warp-half reduction ----
#pragma unroll
    for (int mf = 0; mf < 2; mf++)
#pragma unroll
        for (int i = 0; i < 2; i++) {
            lsum[mf][i] += __shfl_xor_sync(0xffffffffu, lsum[mf][i], 1);
            lsum[mf][i] += __shfl_xor_sync(0xffffffffu, lsum[mf][i], 2);
        }

    // ---- merge n-halves (stage-0 smem reuse, stride 65 = conflict-free) ----
    float* sM = (float*)(smraw + ST);
    if (wn == 1) {
        float* dst = sM + (wm*32 + lane) * 65;
#pragma unroll
        for (int mf = 0; mf < 2; mf++)
#pragma unroll
            for (int j = 0; j < 8; j++)
#pragma unroll
                for (int v = 0; v < 4; v++)
                    dst[mf*32 + j*4 + v] = oacc[mf][j][v];
        if ((lane & 3) == 0) {
            sExc[128 + wm*32 + g]           = lsum[0][0];
            sExc[128 + wm*32 + g + 8]       = lsum[0][1];
            sExc[128 + wm*32 + 16 + g]      = lsum[1][0];
            sExc[128 + wm*32 + 16 + g + 8]  = lsum[1][1];
        }
    }
    __syncthreads();
    if (wn == 0) {
        float* src = sM + (wm*32 + lane) * 65;
        float inv[2][2];
#pragma unroll
        for (int mf = 0; mf < 2; mf++)
#pragma unroll
            for (int i = 0; i < 2; i++)
                inv[mf][i] = 1.0f /
                    (lsum[mf][i] + sExc[128 + wm*32 + mf*16 + i*8 + g]);

        int b = bh >> 4, h = bh & 15;
#pragma unroll
        for (int mf = 0; mf < 2; mf++) {
            int r0 = q0 + wm*32 + mf*16 + g, r1 = r0 + 8;
            size_t row0 = (size_t)(b*TT + r0) * CC + h*DD;
            size_t row1 = (size_t)(b*TT + r1) * CC + h*DD;
#pragma unroll
            for (int j = 0; j < 8; j++) {
                float o0 = oacc[mf][j][0] + src[mf*32 + j*4 + 0];
                float o1 = oacc[mf][j][1] + src[mf*32 + j*4 + 1];
                float o2 = oacc[mf][j][2] + src[mf*32 + j*4 + 2];
                float o3 = oacc[mf][j][3] + src[mf*32 + j*4 + 3];
                int d = 8*j + t2;
                split_st(g_ah, g_al, row0 + d, o0*inv[mf][0], o1*inv[mf][0]);
                split_st(g_ah, g_al, row1 + d, o2*inv[mf][1], o3*inv[mf][1]);
            }
        }
    }
}

// ---------------------------------------------------------------------------
extern "C" void kernel_launch(void* const* d_in, const int* in_sizes, int n_in,
                              void* d_out, int out_size)
{
    (void)in_sizes; (void)n_in; (void)out_size;
    const float* x  = (const float*)d_in[0];
    const float* Wq = (const float*)d_in[1];
    const float* bq = (const float*)d_in[2];
    const float* Wk = (const float*)d_in[3];
    const float* bk = (const float*)d_in[4];
    const float* Wv = (const float*)d_in[5];
    const float* bv = (const float*)d_in[6];
    const float* Wo = (const float*)d_in[7];
    const float* bo = (const float*)d_in[8];
    float* out = (float*)d_out;

    h16 *xh, *xl, *ah, *al, *wh, *wl, *qh, *ql, *kh, *kl, *vh, *vl;
    cudaGetSymbolAddress((void**)&xh, g_xh);
    cudaGetSymbolAddress((void**)&xl, g_xl);
    cudaGetSymbolAddress((void**)&ah, g_ah);
    cudaGetSymbolAddress((void**)&al, g_al);
    cudaGetSymbolAddress((void**)&wh, g_wh);
    cudaGetSymbolAddress((void**)&wl, g_wl);
    cudaGetSymbolAddress((void**)&qh, g_qh);
    cudaGetSymbolAddress((void**)&ql, g_ql);
    cudaGetSymbolAddress((void**)&kh, g_kh);
    cudaGetSymbolAddress((void**)&kl, g_kl);
    cudaGetSymbolAddress((void**)&vh, g_vh);
    cudaGetSymbolAddress((void**)&vl, g_vl);

    // 1. split x
    split_kernel<<<(MM*CC/4)/256, 256>>>(x, xh, xl);

    // 2. transpose+split all 4 weights (one launch)
    tsplit_kernel<<<dim3(CC/32, CC/32, 4), dim3(32, 8)>>>(Wq, Wk, Wv, Wo, wh, wl);

    // 3. fused QKV projection (N=3072); Q pre-scaled by log2e/8 (exp2 domain)
    const int gsm = 2 * GSTG;  // 128 KB
    cudaFuncSetAttribute(gemm_f16x3<0>, cudaFuncAttributeMaxDynamicSharedMemorySize, gsm);
    cudaFuncSetAttribute(gemm_f16x3<1>, cudaFuncAttributeMaxDynamicSharedMemorySize, gsm);
    gemm_f16x3<0><<<dim3(3*CC/128, MM/128), 256, gsm>>>(
        xh, xl, wh, wl, bq, bk, bv,
        nullptr, qh, ql, kh, kl, vh, vl);

    // 4. tensor-core flash attention (4m x 2n layout)
    const int asm_sz = 32768 + 2*65536 + 1024;   // 164864
    cudaFuncSetAttribute(attn_mma, cudaFuncAttributeMaxDynamicSharedMemorySize, asm_sz);
    attn_mma<<<dim3(TT/128, BB*HH), 256, asm_sz>>>();

    // 5. output projection -> d_out (fp32)
    gemm_f16x3<1><<<dim3(CC/128, MM/128), 256, gsm>>>(
        ah, al, wh + (size_t)3*CC*CC, wl + (size_t)3*CC*CC, bo, nullptr, nullptr,
        out, nullptr, nullptr, nullptr, nullptr, nullptr, nullptr);
}

// round 15
// speedup vs baseline: 1.1343x; 1.0435x over previous
#include <cuda_runtime.h>
#include <cuda_fp16.h>
#include <cstdint>

// B=2, T=2048, C=1024, H=16, D=64, causal MHA, fp32 in/out.
#define BB 2
#define TT 2048
#define CC 1024
#define HH 16
#define DD 64
#define MM (BB*TT)

typedef __half h16;

// ---------------- scratch (allocation-free) ----------------
__device__ h16 g_xh[MM*CC], g_xl[MM*CC];
__device__ h16 g_ah[MM*CC], g_al[MM*CC];
__device__ h16 g_wh[4*CC*CC], g_wl[4*CC*CC];   // [Wq|Wk|Wv|Wo] transposed [n][k]
__device__ h16 g_qh[BB*HH*TT*DD], g_ql[BB*HH*TT*DD];
__device__ h16 g_kh[BB*HH*TT*DD], g_kl[BB*HH*TT*DD];
__device__ h16 g_vh[BB*HH*TT*DD], g_vl[BB*HH*TT*DD];

// ---------------- helpers (sm_80-baseline PTX only) ----------------
__device__ __forceinline__ uint32_t smem_u32(const void* p) {
    return (uint32_t)__cvta_generic_to_shared(p);
}

#define CP16(dst, src) \
    asm volatile("cp.async.cg.shared.global [%0], [%1], 16;" :: "r"(dst), "l"(src) : "memory")
#define CP_COMMIT() asm volatile("cp.async.commit_group;" ::: "memory")
#define CP_WAIT(n)  asm volatile("cp.async.wait_group %0;" :: "n"(n) : "memory")

__device__ __forceinline__ void ldm4(uint32_t* r, uint32_t a) {
    asm volatile("ldmatrix.sync.aligned.m8n8.x4.shared.b16 {%0,%1,%2,%3}, [%4];"
                 : "=r"(r[0]), "=r"(r[1]), "=r"(r[2]), "=r"(r[3]) : "r"(a));
}
__device__ __forceinline__ void ldm4t(uint32_t* r, uint32_t a) {
    asm volatile("ldmatrix.sync.aligned.m8n8.x4.trans.shared.b16 {%0,%1,%2,%3}, [%4];"
                 : "=r"(r[0]), "=r"(r[1]), "=r"(r[2]), "=r"(r[3]) : "r"(a));
}
__device__ __forceinline__ void mma_f32(float* d, const uint32_t* a, const uint32_t* b) {
    asm volatile("mma.sync.aligned.m16n8k16.row.col.f32.f16.f16.f32 "
                 "{%0,%1,%2,%3}, {%4,%5,%6,%7}, {%8,%9}, {%0,%1,%2,%3};"
                 : "+f"(d[0]), "+f"(d[1]), "+f"(d[2]), "+f"(d[3])
                 : "r"(a[0]), "r"(a[1]), "r"(a[2]), "r"(a[3]), "r"(b[0]), "r"(b[1]));
}

__device__ __forceinline__ float2 h2f(uint32_t u) {
    __half2 h = *reinterpret_cast<__half2*>(&u);
    return __half22float2(h);
}
__device__ __forceinline__ uint32_t pk2h(float a, float b) {
    __half2 t = __floats2half2_rn(a, b);
    return *reinterpret_cast<uint32_t*>(&t);
}
__device__ __forceinline__ void split_st(h16* hi, h16* lo, size_t off, float a, float b) {
    uint32_t hp = pk2h(a, b);
    float2 back = h2f(hp);
    *(uint32_t*)(hi + off) = hp;
    *(uint32_t*)(lo + off) = pk2h(a - back.x, b - back.y);
}

// ---------------------------------------------------------------------------
__global__ void split_kernel(const float* __restrict__ x,
                             h16* __restrict__ hi, h16* __restrict__ lo) {
    int i = blockIdx.x * blockDim.x + threadIdx.x;
    float4 v = ((const float4*)x)[i];
    split_st(hi, lo, 4*(size_t)i,     v.x, v.y);
    split_st(hi, lo, 4*(size_t)i + 2, v.z, v.w);
}

// ---------------------------------------------------------------------------
__global__ void tsplit_kernel(const float* __restrict__ W0, const float* __restrict__ W1,
                              const float* __restrict__ W2, const float* __restrict__ W3,
                              h16* __restrict__ hi, h16* __restrict__ lo) {
    __shared__ float t[32][33];
    int tx = threadIdx.x, ty = threadIdx.y;          // (32, 8)
    int n0 = blockIdx.x * 32, k0 = blockIdx.y * 32;
    int z = blockIdx.z;
    const float* W = (z == 0) ? W0 : (z == 1) ? W1 : (z == 2) ? W2 : W3;
    h16* hz = hi + (size_t)z * CC * CC;
    h16* lz = lo + (size_t)z * CC * CC;
#pragma unroll
    for (int i = 0; i < 4; i++)
        t[ty + 8*i][tx] = W[(size_t)(k0 + ty + 8*i) * CC + n0 + tx];
    __syncthreads();
#pragma unroll
    for (int i = 0; i < 4; i++) {
        float v = t[tx][ty + 8*i];
        __half h = __float2half_rn(v);
        size_t o = (size_t)(n0 + ty + 8*i) * CC + k0 + tx;
        hz[o] = h;
        lz[o] = __float2half_rn(v - __half2float(h));
    }
}

// ---------------------------------------------------------------------------
// fp16x3 GEMM (uniform f32-acc): 128x128 tile, K-chunk 64, 2-stage cp.async.
// MODE 0: fused QKV (grid.x covers N=3072), split-fp16 out to [B,H,T,D].
// MODE 1: single GEMM (Wo), fp32 [M,N].
// ---------------------------------------------------------------------------
#define GSTG 65536
#define NKT  16

template<int MODE>
__global__ __launch_bounds__(256) void gemm_f16x3(
    const h16* __restrict__ Ah, const h16* __restrict__ Al,
    const h16* __restrict__ Bh, const h16* __restrict__ Bl,
    const float* __restrict__ bias0, const float* __restrict__ bias1,
    const float* __restrict__ bias2,
    float* __restrict__ outF,
    h16* __restrict__ o0h, h16* __restrict__ o0l,
    h16* __restrict__ o1h, h16* __restrict__ o1l,
    h16* __restrict__ o2h, h16* __restrict__ o2l)
{
    extern __shared__ char smraw[];
    const uint32_t sbase = smem_u32(smraw);

    int tid = threadIdx.x, lane = tid & 31, wid = tid >> 5;
    int wm = wid & 1, wn = wid >> 1;
    int m0 = blockIdx.y << 7, n0 = blockIdx.x << 7;

    const float* bias = bias0;
    h16 *oh = o0h, *ol = o0l;
    float scale = 1.0f;
    if (MODE == 0) {
        int sec = n0 >> 10;
        bias = (sec == 0) ? bias0 : (sec == 1) ? bias1 : bias2;
        oh   = (sec == 0) ? o0h   : (sec == 1) ? o1h   : o2h;
        ol   = (sec == 0) ? o0l   : (sec == 1) ? o1l   : o2l;
        // Q pre-scaled by (1/8)*log2(e): softmax runs in exp2 domain.
        scale = (sec == 0) ? 0.180336885f : 1.0f;
    }

    float acc[4][4][4] = {};

    auto load_stage = [&](int kt, int s) {
        uint32_t sb = sbase + (uint32_t)s * GSTG;
#pragma unroll
        for (int i = 0; i < 4; i++) {
            int id = tid + i*256;
            int r = id >> 3, c = id & 7;
            uint32_t phys = (uint32_t)(r*128 + ((c ^ (r & 7)) << 4));
            size_t ga = (size_t)(m0 + r)*CC + kt*64 + c*8;
            size_t gb = (size_t)(n0 + r)*CC + kt*64 + c*8;
            CP16(sb +         phys, Ah + ga);
            CP16(sb + 16384 + phys, Al + ga);
            CP16(sb + 32768 + phys, Bh + gb);
            CP16(sb + 49152 + phys, Bl + gb);
        }
        CP_COMMIT();
    };

    load_stage(0, 0);

    int ahalf = lane >> 4;
    int bhalf = (lane >> 3) & 1;
    int arow = wm*64 + (lane & 15);
    int brow = wn*32 + ((lane >> 4) << 3) + (lane & 7);

    for (int kt = 0; kt < NKT; kt++) {
        if (kt + 1 < NKT) { load_stage(kt + 1, (kt + 1) & 1); CP_WAIT(1); }
        else              { CP_WAIT(0); }
        __syncthreads();

        uint32_t sb = sbase + (uint32_t)(kt & 1) * GSTG;
#pragma unroll
        for (int kk = 0; kk < 4; kk++) {
            uint32_t aswz = (uint32_t)(((2*kk + ahalf) ^ (arow & 7)) << 4);
            uint32_t bswz = (uint32_t)(((2*kk + bhalf) ^ (brow & 7)) << 4);
            uint32_t ah4[4][4], al4[4][4], bh4[2][4], bl4[2][4];
#pragma unroll
            for (int mf = 0; mf < 4; mf++) {
                uint32_t off = (uint32_t)((arow + mf*16) * 128) + aswz;
                ldm4(ah4[mf], sb + off);
                ldm4(al4[mf], sb + 16384 + off);
            }
#pragma unroll
            for (int nh = 0; nh < 2; nh++) {
                uint32_t off = (uint32_t)((brow + nh*16) * 128) + bswz;
                ldm4(bh4[nh], sb + 32768 + off);
                ldm4(bl4[nh], sb + 49152 + off);
            }
#pragma unroll
            for (int mf = 0; mf < 4; mf++)
#pragma unroll
                for (int nf = 0; nf < 4; nf++) {
                    const uint32_t* ph = bh4[nf >> 1] + (nf & 1)*2;
                    const uint32_t* pl = bl4[nf >> 1] + (nf & 1)*2;
                    mma_f32(acc[mf][nf], ah4[mf], ph);
                    mma_f32(acc[mf][nf], ah4[mf], pl);
                    mma_f32(acc[mf][nf], al4[mf], ph);
                }
        }
        __syncthreads();
    }

    int g = lane >> 2, t2 = (lane & 3) * 2;
#pragma unroll
    for (int nf = 0; nf < 4; nf++) {
        int col = n0 + wn*32 + nf*8 + t2;
        int lc = col & (CC - 1);
        float2 bb = *(const float2*)(bias + lc);
#pragma unroll
        for (int mf = 0; mf < 4; mf++) {
            int m1 = m0 + wm*64 + mf*16 + g;
            float v0 = acc[mf][nf][0] + bb.x, v1 = acc[mf][nf][1] + bb.y;
            float v2 = acc[mf][nf][2] + bb.x, v3 = acc[mf][nf][3] + bb.y;
            if (MODE == 0) {
                int h = lc >> 6, d = lc & 63;
                int b1 = m1 >> 11, t1 = m1 & (TT - 1);
                size_t base = ((size_t)(b1*HH + h)*TT) * DD + d;
                split_st(oh, ol, base + (size_t)t1*DD,       v0*scale, v1*scale);
                split_st(oh, ol, base + (size_t)(t1 + 8)*DD, v2*scale, v3*scale);
            } else {
                *(float2*)(outF + (size_t)m1*CC + col)       = make_float2(v0, v1);
                *(float2*)(outF + (size_t)(m1 + 8)*CC + col) = make_float2(v2, v3);
            }
        }
    }
}

// ---------------------------------------------------------------------------
// Tensor-core causal flash attention, fp16 QK x3, PV x2 (Pl*V dropped),
// f32 accumulate, exp2 domain. 4m x 2n warp layout (32 q-rows x 64 keys).
// q-tile 128, k-tile 128, 2-stage KV. smem = 32K Q + 2x64K KV + 1K exch.
// ---------------------------------------------------------------------------
__global__ __launch_bounds__(256) void attn_mma()
{
    extern __shared__ char smraw[];
    const uint32_t sb = smem_u32(smraw);
    const uint32_t QH = 0, QL = 16384, ST = 32768, STSZ = 65536;
    float* sExc = (float*)(smraw + ST + 2*STSZ);    // float[2][128]

    int tid = threadIdx.x, lane = tid & 31, w = tid >> 5;
    int wm = w & 3, wn = w >> 2;
    int bh = blockIdx.y;
    int qt = (int)gridDim.x - 1 - (int)blockIdx.x;   // heavy tiles first
    int q0 = qt * 128;
    int nkt = qt + 1;

    const h16* Qh = g_qh + (size_t)bh*TT*DD;
    const h16* Ql = g_ql + (size_t)bh*TT*DD;
    const h16* Kh = g_kh + (size_t)bh*TT*DD;
    const h16* Kl = g_kl + (size_t)bh*TT*DD;
    const h16* Vh = g_vh + (size_t)bh*TT*DD;
    const h16* Vl = g_vl + (size_t)bh*TT*DD;

    auto load_kv = [&](int kt, int s) {
        uint32_t base = sb + ST + (uint32_t)s * STSZ;
        int k0 = kt * 128;
#pragma unroll
        for (int i = 0; i < 4; i++) {
            int id = tid + i*256;
            int r = id >> 3, c = id & 7;
            uint32_t phys = (uint32_t)(r*128 + ((c ^ (r & 7)) << 4));
            size_t gsrc = (size_t)(k0 + r)*DD + c*8;
            CP16(base +         phys, Kh + gsrc);
            CP16(base + 16384 + phys, Kl + gsrc);
            CP16(base + 32768 + phys, Vh + gsrc);
            CP16(base + 49152 + phys, Vl + gsrc);
        }
        CP_COMMIT();
    };

    // Q tile (128 x 64) hi/lo
#pragma unroll
    for (int m = 0; m < 2; m++)
#pragma unroll
        for (int i = 0; i < 4; i++) {
            int id = tid + i*256;
            int r = id >> 3, c = id & 7;
            uint32_t dst = sb + (m ? QL : QH) + (uint32_t)(r*128 + ((c ^ (r & 7)) << 4));
            const h16* src = (m ? Ql : Qh) + (size_t)(q0 + r)*DD + c*8;
            CP16(dst, src);
        }
    CP_COMMIT();
    load_kv(0, 0);

    CP_WAIT(1);
    __syncthreads();

    float oacc[2][8][4] = {};
    float mrow[2][2] = {{-1e30f, -1e30f}, {-1e30f, -1e30f}};
    float lsum[2][2] = {};

    int g = lane >> 2, t2 = (lane & 3) * 2;
    int ahalf = lane >> 4;
    int bhalf = (lane >> 3) & 1;
    int vi = lane >> 3, vr = lane & 7;

    for (int kt = 0; kt < nkt; kt++) {
        if (kt + 1 < nkt) { load_kv(kt + 1, (kt + 1) & 1); CP_WAIT(1); }
        else              { CP_WAIT(0); }
        __syncthreads();

        int k0 = kt * 128;
        uint32_t st = sb + ST + (uint32_t)(kt & 1) * STSZ;

        // ---- S = Q K^T : rows wm*32 + mf*16, keys wn*64 + ng*16 ----
        float sacc[2][8][4] = {};
#pragma unroll
        for (int kk = 0; kk < 4; kk++) {
            uint32_t qh4[2][4], ql4[2][4];
#pragma unroll
            for (int mf = 0; mf < 2; mf++) {
                int ar = wm*32 + mf*16 + (lane & 15);
                uint32_t off = (uint32_t)(ar*128 + (((2*kk + ahalf) ^ (ar & 7)) << 4));
                ldm4(qh4[mf], sb + QH + off);
                ldm4(ql4[mf], sb + QL + off);
            }
#pragma unroll
            for (int ng = 0; ng < 4; ng++) {
                int br = wn*64 + ng*16 + ((lane >> 4) << 3) + (lane & 7);
                uint32_t off = (uint32_t)(br*128 + (((2*kk + bhalf) ^ (br & 7)) << 4));
                uint32_t kh4[4], kl4[4];
                ldm4(kh4, st + off);
                ldm4(kl4, st + 16384 + off);
#pragma unroll
                for (int mf = 0; mf < 2; mf++) {
                    mma_f32(sacc[mf][2*ng],   qh4[mf], kh4);
                    mma_f32(sacc[mf][2*ng],   qh4[mf], kl4);
                    mma_f32(sacc[mf][2*ng],   ql4[mf], kh4);
                    mma_f32(sacc[mf][2*ng+1], qh4[mf], kh4 + 2);
                    mma_f32(sacc[mf][2*ng+1], qh4[mf], kl4 + 2);
                    mma_f32(sacc[mf][2*ng+1], ql4[mf], kh4 + 2);
                }
            }
        }

        // ---- causal mask (diagonal tile only) ----
        if (kt == nkt - 1) {
#pragma unroll
            for (int mf = 0; mf < 2; mf++) {
                int r0 = q0 + wm*32 + mf*16 + g, r1 = r0 + 8;
#pragma unroll
                for (int j = 0; j < 8; j++) {
                    int col = k0 + wn*64 + 8*j + t2;
                    if (col     > r0) sacc[mf][j][0] = -1e30f;
                    if (col + 1 > r0) sacc[mf][j][1] = -1e30f;
                    if (col     > r1) sacc[mf][j][2] = -1e30f;
                    if (col + 1 > r1) sacc[mf][j][3] = -1e30f;
                }
            }
        }

        // ---- warp-local max ----
        float tm[2][2] = {{-1e30f, -1e30f}, {-1e30f, -1e30f}};
#pragma unroll
        for (int mf = 0; mf < 2; mf++)
#pragma unroll
            for (int j = 0; j < 8; j++) {
                tm[mf][0] = fmaxf(tm[mf][0], fmaxf(sacc[mf][j][0], sacc[mf][j][1]));
                tm[mf][1] = fmaxf(tm[mf][1], fmaxf(sacc[mf][j][2], sacc[mf][j][3]));
            }
#pragma unroll
        for (int mf = 0; mf < 2; mf++)
#pragma unroll
            for (int i = 0; i < 2; i++) {
                tm[mf][i] = fmaxf(tm[mf][i], __shfl_xor_sync(0xffffffffu, tm[mf][i], 1));
                tm[mf][i] = fmaxf(tm[mf][i], __shfl_xor_sync(0xffffffffu, tm[mf][i], 2));
            }

        // ---- cross-warp max exchange ----
        if ((lane & 3) == 0) {
            sExc[wn*128 + wm*32 + g]           = tm[0][0];
            sExc[wn*128 + wm*32 + g + 8]       = tm[0][1];
            sExc[wn*128 + wm*32 + 16 + g]      = tm[1][0];
            sExc[wn*128 + wm*32 + 16 + g + 8]  = tm[1][1];
        }
        __syncthreads();
        float c[2][2];
#pragma unroll
        for (int mf = 0; mf < 2; mf++)
#pragma unroll
            for (int i = 0; i < 2; i++) {
                float peer = sExc[(1 - wn)*128 + wm*32 + mf*16 + i*8 + g];
                float m2 = fmaxf(mrow[mf][i], fmaxf(tm[mf][i], peer));
                c[mf][i] = exp2f(mrow[mf][i] - m2);
                mrow[mf][i] = m2;
            }

        // ---- exp2 + pack (hi only) + partial sums ----
        float ps[2][2] = {};
        uint32_t pfh[2][4][4];
#pragma unroll
        for (int mf = 0; mf < 2; mf++)
#pragma unroll
            for (int kc = 0; kc < 4; kc++)
#pragma unroll
                for (int jj = 0; jj < 2; jj++) {
                    int j = 2*kc + jj;
                    float p0 = exp2f(sacc[mf][j][0] - mrow[mf][0]);
                    float p1 = exp2f(sacc[mf][j][1] - mrow[mf][0]);
                    float p2 = exp2f(sacc[mf][j][2] - mrow[mf][1]);
                    float p3 = exp2f(sacc[mf][j][3] - mrow[mf][1]);
                    ps[mf][0] += p0 + p1; ps[mf][1] += p2 + p3;
                    pfh[mf][kc][2*jj]   = pk2h(p0, p1);
                    pfh[mf][kc][2*jj+1] = pk2h(p2, p3);
                }
#pragma unroll
        for (int mf = 0; mf < 2; mf++) {
            lsum[mf][0] = lsum[mf][0]*c[mf][0] + ps[mf][0];
            lsum[mf][1] = lsum[mf][1]*c[mf][1] + ps[mf][1];
#pragma unroll
            for (int j = 0; j < 8; j++) {
                oacc[mf][j][0] *= c[mf][0]; oacc[mf][j][1] *= c[mf][0];
                oacc[mf][j][2] *= c[mf][1]; oacc[mf][j][3] *= c[mf][1];
            }
        }

        // ---- O += Ph V (hi+lo of V) over this warp's 64 keys ----
#pragma unroll
        for (int kc = 0; kc < 4; kc++)
#pragma unroll
            for (int dg = 0; dg < 4; dg++) {
                int key = wn*64 + kc*16 + 8*(vi & 1) + vr;
                int dc = 2*dg + (vi >> 1);
                uint32_t off = (uint32_t)(key*128 + ((dc ^ (key & 7)) << 4));
                uint32_t vh4[4], vl4[4];
                ldm4t(vh4, st + 32768 + off);
                ldm4t(vl4, st + 49152 + off);
#pragma unroll
                for (int mf = 0; mf < 2; mf++) {
                    mma_f32(oacc[mf][2*dg],   pfh[mf][kc], vh4);
                    mma_f32(oacc[mf][2*dg],   pfh[mf][kc], vl4);
                    mma_f32(oacc[mf][2*dg+1], pfh[mf][kc], vh4 + 2);
                    mma_f32(oacc[mf][2*dg+1], pfh[mf][kc], vl4 + 2);
                }
            }
        __syncthreads();
    }

    // ---- lsum warp-half reduction ----
#pragma unroll
    for (int mf = 0; mf < 2; mf++)
#pragma unroll
        for (int i = 0; i < 2; i++) {
            lsum[mf][i] += __shfl_xor_sync(0xffffffffu, lsum[mf][i], 1);
            lsum[mf][i] += __shfl_xor_sync(0xffffffffu, lsum[mf][i], 2);
        }

    // ---- merge n-halves (stage-0 smem reuse, stride 65 = conflict-free) ----
    float* sM = (float*)(smraw + ST);
    if (wn == 1) {
        float* dst = sM + (wm*32 + lane) * 65;
#pragma unroll
        for (int mf = 0; mf < 2; mf++)
#pragma unroll
            for (int j = 0; j < 8; j++)
#pragma unroll
                for (int v = 0; v < 4; v++)
                    dst[mf*32 + j*4 + v] = oacc[mf][j][v];
        if ((lane & 3) == 0) {
            sExc[128 + wm*32 + g]           = lsum[0][0];
            sExc[128 + wm*32 + g + 8]       = lsum[0][1];
            sExc[128 + wm*32 + 16 + g]      = lsum[1][0];
            sExc[128 + wm*32 + 16 + g + 8]  = lsum[1][1];
        }
    }
    __syncthreads();
    if (wn == 0) {
        float* src = sM + (wm*32 + lane) * 65;
        float inv[2][2];
#pragma unroll
        for (int mf = 0; mf < 2; mf++)
#pragma unroll
            for (int i = 0; i < 2; i++)
                inv[mf][i] = 1.0f /
                    (lsum[mf][i] + sExc[128 + wm*32 + mf*16 + i*8 + g]);

        int b = bh >> 4, h = bh & 15;
#pragma unroll
        for (int mf = 0; mf < 2; mf++) {
            int r0 = q0 + wm*32 + mf*16 + g, r1 = r0 + 8;
            size_t row0 = (size_t)(b*TT + r0) * CC + h*DD;
            size_t row1 = (size_t)(b*TT + r1) * CC + h*DD;
#pragma unroll
            for (int j = 0; j < 8; j++) {
                float o0 = oacc[mf][j][0] + src[mf*32 + j*4 + 0];
                float o1 = oacc[mf][j][1] + src[mf*32 + j*4 + 1];
                float o2 = oacc[mf][j][2] + src[mf*32 + j*4 + 2];
                float o3 = oacc[mf][j][3] + src[mf*32 + j*4 + 3];
                int d = 8*j + t2;
                split_st(g_ah, g_al, row0 + d, o0*inv[mf][0], o1*inv[mf][0]);
                split_st(g_ah, g_al, row1 + d, o2*inv[mf][1], o3*inv[mf][1]);
            }
        }
    }
}

// ---------------------------------------------------------------------------
extern "C" void kernel_launch(void* const* d_in, const int* in_sizes, int n_in,
                              void* d_out, int out_size)
{
    (void)in_sizes; (void)n_in; (void)out_size;
    const float* x  = (const float*)d_in[0];
    const float* Wq = (const float*)d_in[1];
    const float* bq = (const float*)d_in[2];
    const float* Wk = (const float*)d_in[3];
    const float* bk = (const float*)d_in[4];
    const float* Wv = (const float*)d_in[5];
    const float* bv = (const float*)d_in[6];
    const float* Wo = (const float*)d_in[7];
    const float* bo = (const float*)d_in[8];
    float* out = (float*)d_out;

    h16 *xh, *xl, *ah, *al, *wh, *wl, *qh, *ql, *kh, *kl, *vh, *vl;
    cudaGetSymbolAddress((void**)&xh, g_xh);
    cudaGetSymbolAddress((void**)&xl, g_xl);
    cudaGetSymbolAddress((void**)&ah, g_ah);
    cudaGetSymbolAddress((void**)&al, g_al);
    cudaGetSymbolAddress((void**)&wh, g_wh);
    cudaGetSymbolAddress((void**)&wl, g_wl);
    cudaGetSymbolAddress((void**)&qh, g_qh);
    cudaGetSymbolAddress((void**)&ql, g_ql);
    cudaGetSymbolAddress((void**)&kh, g_kh);
    cudaGetSymbolAddress((void**)&kl, g_kl);
    cudaGetSymbolAddress((void**)&vh, g_vh);
    cudaGetSymbolAddress((void**)&vl, g_vl);

    // 1. split x
    split_kernel<<<(MM*CC/4)/256, 256>>>(x, xh, xl);

    // 2. transpose+split all 4 weights (one launch)
    tsplit_kernel<<<dim3(CC/32, CC/32, 4), dim3(32, 8)>>>(Wq, Wk, Wv, Wo, wh, wl);

    // 3. fused QKV projection (N=3072); Q pre-scaled by log2e/8 (exp2 domain)
    const int gsm = 2 * GSTG;  // 128 KB
    cudaFuncSetAttribute(gemm_f16x3<0>, cudaFuncAttributeMaxDynamicSharedMemorySize, gsm);
    cudaFuncSetAttribute(gemm_f16x3<1>, cudaFuncAttributeMaxDynamicSharedMemorySize, gsm);
    gemm_f16x3<0><<<dim3(3*CC/128, MM/128), 256, gsm>>>(
        xh, xl, wh, wl, bq, bk, bv,
        nullptr, qh, ql, kh, kl, vh, vl);

    // 4. tensor-core flash attention (4m x 2n, PV hi-only)
    const int asm_sz = 32768 + 2*65536 + 1024;   // 164864
    cudaFuncSetAttribute(attn_mma, cudaFuncAttributeMaxDynamicSharedMemorySize, asm_sz);
    attn_mma<<<dim3(TT/128, BB*HH), 256, asm_sz>>>();

    // 5. output projection -> d_out (fp32)
    gemm_f16x3<1><<<dim3(CC/128, MM/128), 256, gsm>>>(
        ah, al, wh + (size_t)3*CC*CC, wl + (size_t)3*CC*CC, bo, nullptr, nullptr,
        out, nullptr, nullptr, nullptr, nullptr, nullptr, nullptr);
}

// round 16
// speedup vs baseline: 1.2098x; 1.0666x over previous
#include <cuda_runtime.h>
#include <cuda_fp16.h>
#include <cstdint>

// B=2, T=2048, C=1024, H=16, D=64, causal MHA, fp32 in/out.
#define BB 2
#define TT 2048
#define CC 1024
#define HH 16
#define DD 64
#define MM (BB*TT)

typedef __half h16;

// ---------------- scratch (allocation-free) ----------------
__device__ h16 g_xh[MM*CC], g_xl[MM*CC];
__device__ h16 g_ah[MM*CC], g_al[MM*CC];
__device__ h16 g_wh[4*CC*CC], g_wl[4*CC*CC];   // [Wq|Wk|Wv|Wo] transposed [n][k]
__device__ h16 g_qh[BB*HH*TT*DD], g_ql[BB*HH*TT*DD];
__device__ h16 g_kh[BB*HH*TT*DD], g_kl[BB*HH*TT*DD];
__device__ h16 g_vh[BB*HH*TT*DD], g_vl[BB*HH*TT*DD];

// ---------------- helpers (sm_80-baseline PTX only) ----------------
__device__ __forceinline__ uint32_t smem_u32(const void* p) {
    return (uint32_t)__cvta_generic_to_shared(p);
}

#define CP16(dst, src) \
    asm volatile("cp.async.cg.shared.global [%0], [%1], 16;" :: "r"(dst), "l"(src) : "memory")
#define CP_COMMIT() asm volatile("cp.async.commit_group;" ::: "memory")
#define CP_WAIT(n)  asm volatile("cp.async.wait_group %0;" :: "n"(n) : "memory")

__device__ __forceinline__ void ldm4(uint32_t* r, uint32_t a) {
    asm volatile("ldmatrix.sync.aligned.m8n8.x4.shared.b16 {%0,%1,%2,%3}, [%4];"
                 : "=r"(r[0]), "=r"(r[1]), "=r"(r[2]), "=r"(r[3]) : "r"(a));
}
__device__ __forceinline__ void ldm4t(uint32_t* r, uint32_t a) {
    asm volatile("ldmatrix.sync.aligned.m8n8.x4.trans.shared.b16 {%0,%1,%2,%3}, [%4];"
                 : "=r"(r[0]), "=r"(r[1]), "=r"(r[2]), "=r"(r[3]) : "r"(a));
}
__device__ __forceinline__ void mma_f32(float* d, const uint32_t* a, const uint32_t* b) {
    asm volatile("mma.sync.aligned.m16n8k16.row.col.f32.f16.f16.f32 "
                 "{%0,%1,%2,%3}, {%4,%5,%6,%7}, {%8,%9}, {%0,%1,%2,%3};"
                 : "+f"(d[0]), "+f"(d[1]), "+f"(d[2]), "+f"(d[3])
                 : "r"(a[0]), "r"(a[1]), "r"(a[2]), "r"(a[3]), "r"(b[0]), "r"(b[1]));
}

__device__ __forceinline__ float2 h2f(uint32_t u) {
    __half2 h = *reinterpret_cast<__half2*>(&u);
    return __half22float2(h);
}
__device__ __forceinline__ uint32_t pk2h(float a, float b) {
    __half2 t = __floats2half2_rn(a, b);
    return *reinterpret_cast<uint32_t*>(&t);
}
__device__ __forceinline__ void split_st(h16* hi, h16* lo, size_t off, float a, float b) {
    uint32_t hp = pk2h(a, b);
    float2 back = h2f(hp);
    *(uint32_t*)(hi + off) = hp;
    *(uint32_t*)(lo + off) = pk2h(a - back.x, b - back.y);
}

// ---------------------------------------------------------------------------
__global__ void split_kernel(const float* __restrict__ x,
                             h16* __restrict__ hi, h16* __restrict__ lo) {
    int i = blockIdx.x * blockDim.x + threadIdx.x;
    float4 v = ((const float4*)x)[i];
    split_st(hi, lo, 4*(size_t)i,     v.x, v.y);
    split_st(hi, lo, 4*(size_t)i + 2, v.z, v.w);
}

// ---------------------------------------------------------------------------
__global__ void tsplit_kernel(const float* __restrict__ W0, const float* __restrict__ W1,
                              const float* __restrict__ W2, const float* __restrict__ W3,
                              h16* __restrict__ hi, h16* __restrict__ lo) {
    __shared__ float t[32][33];
    int tx = threadIdx.x, ty = threadIdx.y;          // (32, 8)
    int n0 = blockIdx.x * 32, k0 = blockIdx.y * 32;
    int z = blockIdx.z;
    const float* W = (z == 0) ? W0 : (z == 1) ? W1 : (z == 2) ? W2 : W3;
    h16* hz = hi + (size_t)z * CC * CC;
    h16* lz = lo + (size_t)z * CC * CC;
#pragma unroll
    for (int i = 0; i < 4; i++)
        t[ty + 8*i][tx] = W[(size_t)(k0 + ty + 8*i) * CC + n0 + tx];
    __syncthreads();
#pragma unroll
    for (int i = 0; i < 4; i++) {
        float v = t[tx][ty + 8*i];
        __half h = __float2half_rn(v);
        size_t o = (size_t)(n0 + ty + 8*i) * CC + k0 + tx;
        hz[o] = h;
        lz[o] = __float2half_rn(v - __half2float(h));
    }
}

// ---------------------------------------------------------------------------
// fp16x3 GEMM (uniform f32-acc): 128x128 tile, K-chunk 64, 2-stage cp.async.
// MODE 0: fused QKV (grid.x covers N=3072), split-fp16 out to [B,H,T,D].
// MODE 1: single GEMM (Wo), fp32 [M,N].
// ---------------------------------------------------------------------------
#define GSTG 65536
#define NKT  16

template<int MODE>
__global__ __launch_bounds__(256) void gemm_f16x3(
    const h16* __restrict__ Ah, const h16* __restrict__ Al,
    const h16* __restrict__ Bh, const h16* __restrict__ Bl,
    const float* __restrict__ bias0, const float* __restrict__ bias1,
    const float* __restrict__ bias2,
    float* __restrict__ outF,
    h16* __restrict__ o0h, h16* __restrict__ o0l,
    h16* __restrict__ o1h, h16* __restrict__ o1l,
    h16* __restrict__ o2h, h16* __restrict__ o2l)
{
    extern __shared__ char smraw[];
    const uint32_t sbase = smem_u32(smraw);

    int tid = threadIdx.x, lane = tid & 31, wid = tid >> 5;
    int wm = wid & 1, wn = wid >> 1;
    int m0 = blockIdx.y << 7, n0 = blockIdx.x << 7;

    const float* bias = bias0;
    h16 *oh = o0h, *ol = o0l;
    float scale = 1.0f;
    if (MODE == 0) {
        int sec = n0 >> 10;
        bias = (sec == 0) ? bias0 : (sec == 1) ? bias1 : bias2;
        oh   = (sec == 0) ? o0h   : (sec == 1) ? o1h   : o2h;
        ol   = (sec == 0) ? o0l   : (sec == 1) ? o1l   : o2l;
        // Q pre-scaled by (1/8)*log2(e): softmax runs in exp2 domain.
        scale = (sec == 0) ? 0.180336885f : 1.0f;
    }

    float acc[4][4][4] = {};

    auto load_stage = [&](int kt, int s) {
        uint32_t sb = sbase + (uint32_t)s * GSTG;
#pragma unroll
        for (int i = 0; i < 4; i++) {
            int id = tid + i*256;
            int r = id >> 3, c = id & 7;
            uint32_t phys = (uint32_t)(r*128 + ((c ^ (r & 7)) << 4));
            size_t ga = (size_t)(m0 + r)*CC + kt*64 + c*8;
            size_t gb = (size_t)(n0 + r)*CC + kt*64 + c*8;
            CP16(sb +         phys, Ah + ga);
            CP16(sb + 16384 + phys, Al + ga);
            CP16(sb + 32768 + phys, Bh + gb);
            CP16(sb + 49152 + phys, Bl + gb);
        }
        CP_COMMIT();
    };

    load_stage(0, 0);

    int ahalf = lane >> 4;
    int bhalf = (lane >> 3) & 1;
    int arow = wm*64 + (lane & 15);
    int brow = wn*32 + ((lane >> 4) << 3) + (lane & 7);

    for (int kt = 0; kt < NKT; kt++) {
        if (kt + 1 < NKT) { load_stage(kt + 1, (kt + 1) & 1); CP_WAIT(1); }
        else              { CP_WAIT(0); }
        __syncthreads();

        uint32_t sb = sbase + (uint32_t)(kt & 1) * GSTG;
#pragma unroll
        for (int kk = 0; kk < 4; kk++) {
            uint32_t aswz = (uint32_t)(((2*kk + ahalf) ^ (arow & 7)) << 4);
            uint32_t bswz = (uint32_t)(((2*kk + bhalf) ^ (brow & 7)) << 4);
            uint32_t ah4[4][4], al4[4][4], bh4[2][4], bl4[2][4];
#pragma unroll
            for (int mf = 0; mf < 4; mf++) {
                uint32_t off = (uint32_t)((arow + mf*16) * 128) + aswz;
                ldm4(ah4[mf], sb + off);
                ldm4(al4[mf], sb + 16384 + off);
            }
#pragma unroll
            for (int nh = 0; nh < 2; nh++) {
                uint32_t off = (uint32_t)((brow + nh*16) * 128) + bswz;
                ldm4(bh4[nh], sb + 32768 + off);
                ldm4(bl4[nh], sb + 49152 + off);
            }
#pragma unroll
            for (int mf = 0; mf < 4; mf++)
#pragma unroll
                for (int nf = 0; nf < 4; nf++) {
                    const uint32_t* ph = bh4[nf >> 1] + (nf & 1)*2;
                    const uint32_t* pl = bl4[nf >> 1] + (nf & 1)*2;
                    mma_f32(acc[mf][nf], ah4[mf], ph);
                    mma_f32(acc[mf][nf], ah4[mf], pl);
                    mma_f32(acc[mf][nf], al4[mf], ph);
                }
        }
        __syncthreads();
    }

    int g = lane >> 2, t2 = (lane & 3) * 2;
#pragma unroll
    for (int nf = 0; nf < 4; nf++) {
        int col = n0 + wn*32 + nf*8 + t2;
        int lc = col & (CC - 1);
        float2 bb = *(const float2*)(bias + lc);
#pragma unroll
        for (int mf = 0; mf < 4; mf++) {
            int m1 = m0 + wm*64 + mf*16 + g;
            float v0 = acc[mf][nf][0] + bb.x, v1 = acc[mf][nf][1] + bb.y;
            float v2 = acc[mf][nf][2] + bb.x, v3 = acc[mf][nf][3] + bb.y;
            if (MODE == 0) {
                int h = lc >> 6, d = lc & 63;
                int b1 = m1 >> 11, t1 = m1 & (TT - 1);
                size_t base = ((size_t)(b1*HH + h)*TT) * DD + d;
                split_st(oh, ol, base + (size_t)t1*DD,       v0*scale, v1*scale);
                split_st(oh, ol, base + (size_t)(t1 + 8)*DD, v2*scale, v3*scale);
            } else {
                *(float2*)(outF + (size_t)m1*CC + col)       = make_float2(v0, v1);
                *(float2*)(outF + (size_t)(m1 + 8)*CC + col) = make_float2(v2, v3);
            }
        }
    }
}

// ---------------------------------------------------------------------------
// Tensor-core causal flash attention, fp16: QK x3, PV = Ph*Vh only
// (Pl and Vl corrections dropped — calibrated linear error class).
// f32 accumulate, exp2 domain. 4m x 2n warp layout (32 q-rows x 64 keys).
// q-tile 128, k-tile 128, 2-stage KV (Kh,Kl,Vh = 48KB/stage).
// smem = 32K Q + 2x48K KV + 1K exch = 129.8KB.
// ---------------------------------------------------------------------------
__global__ __launch_bounds__(256) void attn_mma()
{
    extern __shared__ char smraw[];
    const uint32_t sb = smem_u32(smraw);
    const uint32_t QH = 0, QL = 16384, ST = 32768, STSZ = 49152;
    float* sExc = (float*)(smraw + ST + 2*STSZ);    // float[2][128]

    int tid = threadIdx.x, lane = tid & 31, w = tid >> 5;
    int wm = w & 3, wn = w >> 2;
    int bh = blockIdx.y;
    int qt = (int)gridDim.x - 1 - (int)blockIdx.x;   // heavy tiles first
    int q0 = qt * 128;
    int nkt = qt + 1;

    const h16* Qh = g_qh + (size_t)bh*TT*DD;
    const h16* Ql = g_ql + (size_t)bh*TT*DD;
    const h16* Kh = g_kh + (size_t)bh*TT*DD;
    const h16* Kl = g_kl + (size_t)bh*TT*DD;
    const h16* Vh = g_vh + (size_t)bh*TT*DD;

    auto load_kv = [&](int kt, int s) {
        uint32_t base = sb + ST + (uint32_t)s * STSZ;
        int k0 = kt * 128;
#pragma unroll
        for (int i = 0; i < 4; i++) {
            int id = tid + i*256;
            int r = id >> 3, c = id & 7;
            uint32_t phys = (uint32_t)(r*128 + ((c ^ (r & 7)) << 4));
            size_t gsrc = (size_t)(k0 + r)*DD + c*8;
            CP16(base +         phys, Kh + gsrc);
            CP16(base + 16384 + phys, Kl + gsrc);
            CP16(base + 32768 + phys, Vh + gsrc);
        }
        CP_COMMIT();
    };

    // Q tile (128 x 64) hi/lo
#pragma unroll
    for (int m = 0; m < 2; m++)
#pragma unroll
        for (int i = 0; i < 4; i++) {
            int id = tid + i*256;
            int r = id >> 3, c = id & 7;
            uint32_t dst = sb + (m ? QL : QH) + (uint32_t)(r*128 + ((c ^ (r & 7)) << 4));
            const h16* src = (m ? Ql : Qh) + (size_t)(q0 + r)*DD + c*8;
            CP16(dst, src);
        }
    CP_COMMIT();
    load_kv(0, 0);

    CP_WAIT(1);
    __syncthreads();

    float oacc[2][8][4] = {};
    float mrow[2][2] = {{-1e30f, -1e30f}, {-1e30f, -1e30f}};
    float lsum[2][2] = {};

    int g = lane >> 2, t2 = (lane & 3) * 2;
    int ahalf = lane >> 4;
    int bhalf = (lane >> 3) & 1;
    int vi = lane >> 3, vr = lane & 7;

    for (int kt = 0; kt < nkt; kt++) {
        if (kt + 1 < nkt) { load_kv(kt + 1, (kt + 1) & 1); CP_WAIT(1); }
        else              { CP_WAIT(0); }
        __syncthreads();

        int k0 = kt * 128;
        uint32_t st = sb + ST + (uint32_t)(kt & 1) * STSZ;

        // ---- S = Q K^T : rows wm*32 + mf*16, keys wn*64 + ng*16 ----
        float sacc[2][8][4] = {};
#pragma unroll
        for (int kk = 0; kk < 4; kk++) {
            uint32_t qh4[2][4], ql4[2][4];
#pragma unroll
            for (int mf = 0; mf < 2; mf++) {
                int ar = wm*32 + mf*16 + (lane & 15);
                uint32_t off = (uint32_t)(ar*128 + (((2*kk + ahalf) ^ (ar & 7)) << 4));
                ldm4(qh4[mf], sb + QH + off);
                ldm4(ql4[mf], sb + QL + off);
            }
#pragma unroll
            for (int ng = 0; ng < 4; ng++) {
                int br = wn*64 + ng*16 + ((lane >> 4) << 3) + (lane & 7);
                uint32_t off = (uint32_t)(br*128 + (((2*kk + bhalf) ^ (br & 7)) << 4));
                uint32_t kh4[4], kl4[4];
                ldm4(kh4, st + off);
                ldm4(kl4, st + 16384 + off);
#pragma unroll
                for (int mf = 0; mf < 2; mf++) {
                    mma_f32(sacc[mf][2*ng],   qh4[mf], kh4);
                    mma_f32(sacc[mf][2*ng],   qh4[mf], kl4);
                    mma_f32(sacc[mf][2*ng],   ql4[mf], kh4);
                    mma_f32(sacc[mf][2*ng+1], qh4[mf], kh4 + 2);
                    mma_f32(sacc[mf][2*ng+1], qh4[mf], kl4 + 2);
                    mma_f32(sacc[mf][2*ng+1], ql4[mf], kh4 + 2);
                }
            }
        }

        // ---- causal mask (diagonal tile only) ----
        if (kt == nkt - 1) {
#pragma unroll
            for (int mf = 0; mf < 2; mf++) {
                int r0 = q0 + wm*32 + mf*16 + g, r1 = r0 + 8;
#pragma unroll
                for (int j = 0; j < 8; j++) {
                    int col = k0 + wn*64 + 8*j + t2;
                    if (col     > r0) sacc[mf][j][0] = -1e30f;
                    if (col + 1 > r0) sacc[mf][j][1] = -1e30f;
                    if (col     > r1) sacc[mf][j][2] = -1e30f;
                    if (col + 1 > r1) sacc[mf][j][3] = -1e30f;
                }
            }
        }

        // ---- warp-local max ----
        float tm[2][2] = {{-1e30f, -1e30f}, {-1e30f, -1e30f}};
#pragma unroll
        for (int mf = 0; mf < 2; mf++)
#pragma unroll
            for (int j = 0; j < 8; j++) {
                tm[mf][0] = fmaxf(tm[mf][0], fmaxf(sacc[mf][j][0], sacc[mf][j][1]));
                tm[mf][1] = fmaxf(tm[mf][1], fmaxf(sacc[mf][j][2], sacc[mf][j][3]));
            }
#pragma unroll
        for (int mf = 0; mf < 2; mf++)
#pragma unroll
            for (int i = 0; i < 2; i++) {
                tm[mf][i] = fmaxf(tm[mf][i], __shfl_xor_sync(0xffffffffu, tm[mf][i], 1));
                tm[mf][i] = fmaxf(tm[mf][i], __shfl_xor_sync(0xffffffffu, tm[mf][i], 2));
            }

        // ---- cross-warp max exchange ----
        if ((lane & 3) == 0) {
            sExc[wn*128 + wm*32 + g]           = tm[0][0];
            sExc[wn*128 + wm*32 + g + 8]       = tm[0][1];
            sExc[wn*128 + wm*32 + 16 + g]      = tm[1][0];
            sExc[wn*128 + wm*32 + 16 + g + 8]  = tm[1][1];
        }
        __syncthreads();
        float c[2][2];
#pragma unroll
        for (int mf = 0; mf < 2; mf++)
#pragma unroll
            for (int i = 0; i < 2; i++) {
                float peer = sExc[(1 - wn)*128 + wm*32 + mf*16 + i*8 + g];
                float m2 = fmaxf(mrow[mf][i], fmaxf(tm[mf][i], peer));
                c[mf][i] = exp2f(mrow[mf][i] - m2);
                mrow[mf][i] = m2;
            }

        // ---- exp2 + pack (hi only) + partial sums ----
        float ps[2][2] = {};
        uint32_t pfh[2][4][4];
#pragma unroll
        for (int mf = 0; mf < 2; mf++)
#pragma unroll
            for (int kc = 0; kc < 4; kc++)
#pragma unroll
                for (int jj = 0; jj < 2; jj++) {
                    int j = 2*kc + jj;
                    float p0 = exp2f(sacc[mf][j][0] - mrow[mf][0]);
                    float p1 = exp2f(sacc[mf][j][1] - mrow[mf][0]);
                    float p2 = exp2f(sacc[mf][j][2] - mrow[mf][1]);
                    float p3 = exp2f(sacc[mf][j][3] - mrow[mf][1]);
                    ps[mf][0] += p0 + p1; ps[mf][1] += p2 + p3;
                    pfh[mf][kc][2*jj]   = pk2h(p0, p1);
                    pfh[mf][kc][2*jj+1] = pk2h(p2, p3);
                }
#pragma unroll
        for (int mf = 0; mf < 2; mf++) {
            lsum[mf][0] = lsum[mf][0]*c[mf][0] + ps[mf][0];
            lsum[mf][1] = lsum[mf][1]*c[mf][1] + ps[mf][1];
#pragma unroll
            for (int j = 0; j < 8; j++) {
                oacc[mf][j][0] *= c[mf][0]; oacc[mf][j][1] *= c[mf][0];
                oacc[mf][j][2] *= c[mf][1]; oacc[mf][j][3] *= c[mf][1];
            }
        }

        // ---- O += Ph Vh over this warp's 64 keys ----
#pragma unroll
        for (int kc = 0; kc < 4; kc++)
#pragma unroll
            for (int dg = 0; dg < 4; dg++) {
                int key = wn*64 + kc*16 + 8*(vi & 1) + vr;
                int dc = 2*dg + (vi >> 1);
                uint32_t off = (uint32_t)(key*128 + ((dc ^ (key & 7)) << 4));
                uint32_t vh4[4];
                ldm4t(vh4, st + 32768 + off);
#pragma unroll
                for (int mf = 0; mf < 2; mf++) {
                    mma_f32(oacc[mf][2*dg],   pfh[mf][kc], vh4);
                    mma_f32(oacc[mf][2*dg+1], pfh[mf][kc], vh4 + 2);
                }
            }
        __syncthreads();
    }

    // ---- lsum warp-half reduction ----
#pragma unroll
    for (int mf = 0; mf < 2; mf++)
#pragma unroll
        for (int i = 0; i < 2; i++) {
            lsum[mf][i] += __shfl_xor_sync(0xffffffffu, lsum[mf][i], 1);
            lsum[mf][i] += __shfl_xor_sync(0xffffffffu, lsum[mf][i], 2);
        }

    // ---- merge n-halves (stage-0 smem reuse, stride 65 = conflict-free) ----
    float* sM = (float*)(smraw + ST);
    if (wn == 1) {
        float* dst = sM + (wm*32 + lane) * 65;
#pragma unroll
        for (int mf = 0; mf < 2; mf++)
#pragma unroll
            for (int j = 0; j < 8; j++)
#pragma unroll
                for (int v = 0; v < 4; v++)
                    dst[mf*32 + j*4 + v] = oacc[mf][j][v];
        if ((lane & 3) == 0) {
            sExc[128 + wm*32 + g]           = lsum[0][0];
            sExc[128 + wm*32 + g + 8]       = lsum[0][1];
            sExc[128 + wm*32 + 16 + g]      = lsum[1][0];
            sExc[128 + wm*32 + 16 + g + 8]  = lsum[1][1];
        }
    }
    __syncthreads();
    if (wn == 0) {
        float* src = sM + (wm*32 + lane) * 65;
        float inv[2][2];
#pragma unroll
        for (int mf = 0; mf < 2; mf++)
#pragma unroll
            for (int i = 0; i < 2; i++)
                inv[mf][i] = 1.0f /
                    (lsum[mf][i] + sExc[128 + wm*32 + mf*16 + i*8 + g]);

        int b = bh >> 4, h = bh & 15;
#pragma unroll
        for (int mf = 0; mf < 2; mf++) {
            int r0 = q0 + wm*32 + mf*16 + g, r1 = r0 + 8;
            size_t row0 = (size_t)(b*TT + r0) * CC + h*DD;
            size_t row1 = (size_t)(b*TT + r1) * CC + h*DD;
#pragma unroll
            for (int j = 0; j < 8; j++) {
                float o0 = oacc[mf][j][0] + src[mf*32 + j*4 + 0];
                float o1 = oacc[mf][j][1] + src[mf*32 + j*4 + 1];
                float o2 = oacc[mf][j][2] + src[mf*32 + j*4 + 2];
                float o3 = oacc[mf][j][3] + src[mf*32 + j*4 + 3];
                int d = 8*j + t2;
                split_st(g_ah, g_al, row0 + d, o0*inv[mf][0], o1*inv[mf][0]);
                split_st(g_ah, g_al, row1 + d, o2*inv[mf][1], o3*inv[mf][1]);
            }
        }
    }
}

// ---------------------------------------------------------------------------
extern "C" void kernel_launch(void* const* d_in, const int* in_sizes, int n_in,
                              void* d_out, int out_size)
{
    (void)in_sizes; (void)n_in; (void)out_size;
    const float* x  = (const float*)d_in[0];
    const float* Wq = (const float*)d_in[1];
    const float* bq = (const float*)d_in[2];
    const float* Wk = (const float*)d_in[3];
    const float* bk = (const float*)d_in[4];
    const float* Wv = (const float*)d_in[5];
    const float* bv = (const float*)d_in[6];
    const float* Wo = (const float*)d_in[7];
    const float* bo = (const float*)d_in[8];
    float* out = (float*)d_out;

    h16 *xh, *xl, *ah, *al, *wh, *wl, *qh, *ql, *kh, *kl, *vh, *vl;
    cudaGetSymbolAddress((void**)&xh, g_xh);
    cudaGetSymbolAddress((void**)&xl, g_xl);
    cudaGetSymbolAddress((void**)&ah, g_ah);
    cudaGetSymbolAddress((void**)&al, g_al);
    cudaGetSymbolAddress((void**)&wh, g_wh);
    cudaGetSymbolAddress((void**)&wl, g_wl);
    cudaGetSymbolAddress((void**)&qh, g_qh);
    cudaGetSymbolAddress((void**)&ql, g_ql);
    cudaGetSymbolAddress((void**)&kh, g_kh);
    cudaGetSymbolAddress((void**)&kl, g_kl);
    cudaGetSymbolAddress((void**)&vh, g_vh);
    cudaGetSymbolAddress((void**)&vl, g_vl);

    // 1. split x
    split_kernel<<<(MM*CC/4)/256, 256>>>(x, xh, xl);

    // 2. transpose+split all 4 weights (one launch)
    tsplit_kernel<<<dim3(CC/32, CC/32, 4), dim3(32, 8)>>>(Wq, Wk, Wv, Wo, wh, wl);

    // 3. fused QKV projection (N=3072); Q pre-scaled by log2e/8 (exp2 domain)
    const int gsm = 2 * GSTG;  // 128 KB
    cudaFuncSetAttribute(gemm_f16x3<0>, cudaFuncAttributeMaxDynamicSharedMemorySize, gsm);
    cudaFuncSetAttribute(gemm_f16x3<1>, cudaFuncAttributeMaxDynamicSharedMemorySize, gsm);
    gemm_f16x3<0><<<dim3(3*CC/128, MM/128), 256, gsm>>>(
        xh, xl, wh, wl, bq, bk, bv,
        nullptr, qh, ql, kh, kl, vh, vl);

    // 4. tensor-core flash attention (4m x 2n, PV = Ph*Vh)
    const int asm_sz = 32768 + 2*49152 + 1024;   // 131072 + 1024 = 132096
    cudaFuncSetAttribute(attn_mma, cudaFuncAttributeMaxDynamicSharedMemorySize, asm_sz);
    attn_mma<<<dim3(TT/128, BB*HH), 256, asm_sz>>>();

    // 5. output projection -> d_out (fp32)
    gemm_f16x3<1><<<dim3(CC/128, MM/128), 256, gsm>>>(
        ah, al, wh + (size_t)3*CC*CC, wl + (size_t)3*CC*CC, bo, nullptr, nullptr,
        out, nullptr, nullptr, nullptr, nullptr, nullptr, nullptr);
}

// round 17
// speedup vs baseline: 1.5212x; 1.2574x over previous
#include <cuda_runtime.h>
#include <cuda_fp16.h>
#include <cstdint>

// B=2, T=2048, C=1024, H=16, D=64, causal MHA, fp32 in/out.
#define BB 2
#define TT 2048
#define CC 1024
#define HH 16
#define DD 64
#define MM (BB*TT)

typedef __half h16;

// ---------------- scratch (allocation-free) ----------------
__device__ h16 g_xh[MM*CC], g_xl[MM*CC];
__device__ h16 g_ah[MM*CC];                      // attended, hi only
__device__ h16 g_wh[4*CC*CC], g_wl[4*CC*CC];    // [Wq|Wk|Wv|Wo] transposed [n][k]
__device__ h16 g_qh[BB*HH*TT*DD], g_ql[BB*HH*TT*DD];
__device__ h16 g_kh[BB*HH*TT*DD], g_kl[BB*HH*TT*DD];
__device__ h16 g_vh[BB*HH*TT*DD];                // V, hi only

// ---------------- helpers (sm_80-baseline PTX only) ----------------
__device__ __forceinline__ uint32_t smem_u32(const void* p) {
    return (uint32_t)__cvta_generic_to_shared(p);
}

#define CP16(dst, src) \
    asm volatile("cp.async.cg.shared.global [%0], [%1], 16;" :: "r"(dst), "l"(src) : "memory")
#define CP_COMMIT() asm volatile("cp.async.commit_group;" ::: "memory")
#define CP_WAIT(n)  asm volatile("cp.async.wait_group %0;" :: "n"(n) : "memory")

__device__ __forceinline__ void ldm4(uint32_t* r, uint32_t a) {
    asm volatile("ldmatrix.sync.aligned.m8n8.x4.shared.b16 {%0,%1,%2,%3}, [%4];"
                 : "=r"(r[0]), "=r"(r[1]), "=r"(r[2]), "=r"(r[3]) : "r"(a));
}
__device__ __forceinline__ void ldm4t(uint32_t* r, uint32_t a) {
    asm volatile("ldmatrix.sync.aligned.m8n8.x4.trans.shared.b16 {%0,%1,%2,%3}, [%4];"
                 : "=r"(r[0]), "=r"(r[1]), "=r"(r[2]), "=r"(r[3]) : "r"(a));
}
__device__ __forceinline__ void mma_f32(float* d, const uint32_t* a, const uint32_t* b) {
    asm volatile("mma.sync.aligned.m16n8k16.row.col.f32.f16.f16.f32 "
                 "{%0,%1,%2,%3}, {%4,%5,%6,%7}, {%8,%9}, {%0,%1,%2,%3};"
                 : "+f"(d[0]), "+f"(d[1]), "+f"(d[2]), "+f"(d[3])
                 : "r"(a[0]), "r"(a[1]), "r"(a[2]), "r"(a[3]), "r"(b[0]), "r"(b[1]));
}

__device__ __forceinline__ float2 h2f(uint32_t u) {
    __half2 h = *reinterpret_cast<__half2*>(&u);
    return __half22float2(h);
}
__device__ __forceinline__ uint32_t pk2h(float a, float b) {
    __half2 t = __floats2half2_rn(a, b);
    return *reinterpret_cast<uint32_t*>(&t);
}
__device__ __forceinline__ void split_st(h16* hi, h16* lo, size_t off, float a, float b) {
    uint32_t hp = pk2h(a, b);
    float2 back = h2f(hp);
    *(uint32_t*)(hi + off) = hp;
    *(uint32_t*)(lo + off) = pk2h(a - back.x, b - back.y);
}

// ---------------------------------------------------------------------------
__global__ void split_kernel(const float* __restrict__ x,
                             h16* __restrict__ hi, h16* __restrict__ lo) {
    int i = blockIdx.x * blockDim.x + threadIdx.x;
    float4 v = ((const float4*)x)[i];
    split_st(hi, lo, 4*(size_t)i,     v.x, v.y);
    split_st(hi, lo, 4*(size_t)i + 2, v.z, v.w);
}

// ---------------------------------------------------------------------------
__global__ void tsplit_kernel(const float* __restrict__ W0, const float* __restrict__ W1,
                              const float* __restrict__ W2, const float* __restrict__ W3,
                              h16* __restrict__ hi, h16* __restrict__ lo) {
    __shared__ float t[32][33];
    int tx = threadIdx.x, ty = threadIdx.y;          // (32, 8)
    int n0 = blockIdx.x * 32, k0 = blockIdx.y * 32;
    int z = blockIdx.z;
    const float* W = (z == 0) ? W0 : (z == 1) ? W1 : (z == 2) ? W2 : W3;
    h16* hz = hi + (size_t)z * CC * CC;
    h16* lz = lo + (size_t)z * CC * CC;
#pragma unroll
    for (int i = 0; i < 4; i++)
        t[ty + 8*i][tx] = W[(size_t)(k0 + ty + 8*i) * CC + n0 + tx];
    __syncthreads();
#pragma unroll
    for (int i = 0; i < 4; i++) {
        float v = t[tx][ty + 8*i];
        __half h = __float2half_rn(v);
        size_t o = (size_t)(n0 + ty + 8*i) * CC + k0 + tx;
        hz[o] = h;
        lz[o] = __float2half_rn(v - __half2float(h));
    }
}

// ---------------------------------------------------------------------------
// fp16 GEMM, templated on product count.
// NPROD=3: C = Ah*Bh + Ah*Bl + Al*Bh (stage 64KB).  NPROD=1: C = Ah*Bh (32KB).
// MODE 0: QK fused (grid.x covers N=2048), split-fp16 out to [B,H,T,D],
//         section 0 = Q (scaled log2e/8), section 1 = K.
// MODE 1: V projection, fp16-hi out to [B,H,T,D].
// MODE 2: Wo projection, fp32 out [M,N].
// 128x128 tile, K-chunk 64, 2-stage cp.async, 8 warps (64x32 each).
// ---------------------------------------------------------------------------
#define NKT 16

template<int MODE, int NPROD>
__global__ __launch_bounds__(256) void gemm_f16(
    const h16* __restrict__ Ah, const h16* __restrict__ Al,
    const h16* __restrict__ Bh, const h16* __restrict__ Bl,
    const float* __restrict__ bias0, const float* __restrict__ bias1,
    float* __restrict__ outF,
    h16* __restrict__ o0h, h16* __restrict__ o0l,
    h16* __restrict__ o1h, h16* __restrict__ o1l)
{
    const uint32_t STG  = (NPROD == 3) ? 65536u : 32768u;
    const uint32_t BOFF = (NPROD == 3) ? 32768u : 16384u;

    extern __shared__ char smraw[];
    const uint32_t sbase = smem_u32(smraw);

    int tid = threadIdx.x, lane = tid & 31, wid = tid >> 5;
    int wm = wid & 1, wn = wid >> 1;
    int m0 = blockIdx.y << 7, n0 = blockIdx.x << 7;

    const float* bias = bias0;
    h16 *oh = o0h, *ol = o0l;
    float scale = (MODE == 0) ? 0.180336885f : 1.0f;   // Q: (1/8)*log2(e)
    if (MODE == 0 && (n0 >> 10)) { bias = bias1; oh = o1h; ol = o1l; scale = 1.0f; }

    float acc[4][4][4] = {};

    auto load_stage = [&](int kt, int s) {
        uint32_t sb = sbase + (uint32_t)s * STG;
#pragma unroll
        for (int i = 0; i < 4; i++) {
            int id = tid + i*256;
            int r = id >> 3, c = id & 7;
            uint32_t phys = (uint32_t)(r*128 + ((c ^ (r & 7)) << 4));
            size_t ga = (size_t)(m0 + r)*CC + kt*64 + c*8;
            size_t gb = (size_t)(n0 + r)*CC + kt*64 + c*8;
            CP16(sb +        phys, Ah + ga);
            CP16(sb + BOFF + phys, Bh + gb);
            if (NPROD == 3) {
                CP16(sb + 16384 + phys, Al + ga);
                CP16(sb + BOFF + 16384 + phys, Bl + gb);
            }
        }
        CP_COMMIT();
    };

    load_stage(0, 0);

    int ahalf = lane >> 4;
    int bhalf = (lane >> 3) & 1;
    int arow = wm*64 + (lane & 15);
    int brow = wn*32 + ((lane >> 4) << 3) + (lane & 7);

    for (int kt = 0; kt < NKT; kt++) {
        if (kt + 1 < NKT) { load_stage(kt + 1, (kt + 1) & 1); CP_WAIT(1); }
        else              { CP_WAIT(0); }
        __syncthreads();

        uint32_t sb = sbase + (uint32_t)(kt & 1) * STG;
#pragma unroll
        for (int kk = 0; kk < 4; kk++) {
            uint32_t aswz = (uint32_t)(((2*kk + ahalf) ^ (arow & 7)) << 4);
            uint32_t bswz = (uint32_t)(((2*kk + bhalf) ^ (brow & 7)) << 4);
            uint32_t ah4[4][4], al4[4][4], bh4[2][4], bl4[2][4];
#pragma unroll
            for (int mf = 0; mf < 4; mf++) {
                uint32_t off = (uint32_t)((arow + mf*16) * 128) + aswz;
                ldm4(ah4[mf], sb + off);
                if (NPROD == 3) ldm4(al4[mf], sb + 16384 + off);
            }
#pragma unroll
            for (int nh = 0; nh < 2; nh++) {
                uint32_t off = (uint32_t)((brow + nh*16) * 128) + bswz;
                ldm4(bh4[nh], sb + BOFF + off);
                if (NPROD == 3) ldm4(bl4[nh], sb + BOFF + 16384 + off);
            }
#pragma unroll
            for (int mf = 0; mf < 4; mf++)
#pragma unroll
                for (int nf = 0; nf < 4; nf++) {
                    const uint32_t* ph = bh4[nf >> 1] + (nf & 1)*2;
                    mma_f32(acc[mf][nf], ah4[mf], ph);
                    if (NPROD == 3) {
                        const uint32_t* pl = bl4[nf >> 1] + (nf & 1)*2;
                        mma_f32(acc[mf][nf], ah4[mf], pl);
                        mma_f32(acc[mf][nf], al4[mf], ph);
                    }
                }
        }
        __syncthreads();
    }

    int g = lane >> 2, t2 = (lane & 3) * 2;
#pragma unroll
    for (int nf = 0; nf < 4; nf++) {
        int col = n0 + wn*32 + nf*8 + t2;
        int lc = col & (CC - 1);
        float2 bb = *(const float2*)(bias + lc);
#pragma unroll
        for (int mf = 0; mf < 4; mf++) {
            int m1 = m0 + wm*64 + mf*16 + g;
            float v0 = acc[mf][nf][0] + bb.x, v1 = acc[mf][nf][1] + bb.y;
            float v2 = acc[mf][nf][2] + bb.x, v3 = acc[mf][nf][3] + bb.y;
            if (MODE == 0 || MODE == 1) {
                int h = lc >> 6, d = lc & 63;
                int b1 = m1 >> 11, t1 = m1 & (TT - 1);
                size_t base = ((size_t)(b1*HH + h)*TT) * DD + d;
                if (MODE == 0) {
                    split_st(oh, ol, base + (size_t)t1*DD,       v0*scale, v1*scale);
                    split_st(oh, ol, base + (size_t)(t1 + 8)*DD, v2*scale, v3*scale);
                } else {
                    *(uint32_t*)(oh + base + (size_t)t1*DD)       = pk2h(v0, v1);
                    *(uint32_t*)(oh + base + (size_t)(t1 + 8)*DD) = pk2h(v2, v3);
                }
            } else {
                *(float2*)(outF + (size_t)m1*CC + col)       = make_float2(v0, v1);
                *(float2*)(outF + (size_t)(m1 + 8)*CC + col) = make_float2(v2, v3);
            }
        }
    }
}

// ---------------------------------------------------------------------------
// Tensor-core causal flash attention, fp16: QK x3, PV = Ph*Vh.
// f32 accumulate, exp2 domain. 4m x 2n warp layout (32 q-rows x 64 keys).
// q-tile 128, k-tile 128, 2-stage KV (Kh,Kl,Vh = 48KB/stage).
// Epilogue writes hi-only attended (Wo GEMM is x1).
// ---------------------------------------------------------------------------
__global__ __launch_bounds__(256) void attn_mma()
{
    extern __shared__ char smraw[];
    const uint32_t sb = smem_u32(smraw);
    const uint32_t QH = 0, QL = 16384, ST = 32768, STSZ = 49152;
    float* sExc = (float*)(smraw + ST + 2*STSZ);    // float[2][128]

    int tid = threadIdx.x, lane = tid & 31, w = tid >> 5;
    int wm = w & 3, wn = w >> 2;
    int bh = blockIdx.y;
    int qt = (int)gridDim.x - 1 - (int)blockIdx.x;   // heavy tiles first
    int q0 = qt * 128;
    int nkt = qt + 1;

    const h16* Qh = g_qh + (size_t)bh*TT*DD;
    const h16* Ql = g_ql + (size_t)bh*TT*DD;
    const h16* Kh = g_kh + (size_t)bh*TT*DD;
    const h16* Kl = g_kl + (size_t)bh*TT*DD;
    const h16* Vh = g_vh + (size_t)bh*TT*DD;

    auto load_kv = [&](int kt, int s) {
        uint32_t base = sb + ST + (uint32_t)s * STSZ;
        int k0 = kt * 128;
#pragma unroll
        for (int i = 0; i < 4; i++) {
            int id = tid + i*256;
            int r = id >> 3, c = id & 7;
            uint32_t phys = (uint32_t)(r*128 + ((c ^ (r & 7)) << 4));
            size_t gsrc = (size_t)(k0 + r)*DD + c*8;
            CP16(base +         phys, Kh + gsrc);
            CP16(base + 16384 + phys, Kl + gsrc);
            CP16(base + 32768 + phys, Vh + gsrc);
        }
        CP_COMMIT();
    };

    // Q tile (128 x 64) hi/lo
#pragma unroll
    for (int m = 0; m < 2; m++)
#pragma unroll
        for (int i = 0; i < 4; i++) {
            int id = tid + i*256;
            int r = id >> 3, c = id & 7;
            uint32_t dst = sb + (m ? QL : QH) + (uint32_t)(r*128 + ((c ^ (r & 7)) << 4));
            const h16* src = (m ? Ql : Qh) + (size_t)(q0 + r)*DD + c*8;
            CP16(dst, src);
        }
    CP_COMMIT();
    load_kv(0, 0);

    CP_WAIT(1);
    __syncthreads();

    float oacc[2][8][4] = {};
    float mrow[2][2] = {{-1e30f, -1e30f}, {-1e30f, -1e30f}};
    float lsum[2][2] = {};

    int g = lane >> 2, t2 = (lane & 3) * 2;
    int ahalf = lane >> 4;
    int bhalf = (lane >> 3) & 1;
    int vi = lane >> 3, vr = lane & 7;

    for (int kt = 0; kt < nkt; kt++) {
        if (kt + 1 < nkt) { load_kv(kt + 1, (kt + 1) & 1); CP_WAIT(1); }
        else              { CP_WAIT(0); }
        __syncthreads();

        int k0 = kt * 128;
        uint32_t st = sb + ST + (uint32_t)(kt & 1) * STSZ;

        // ---- S = Q K^T : rows wm*32 + mf*16, keys wn*64 + ng*16 ----
        float sacc[2][8][4] = {};
#pragma unroll
        for (int kk = 0; kk < 4; kk++) {
            uint32_t qh4[2][4], ql4[2][4];
#pragma unroll
            for (int mf = 0; mf < 2; mf++) {
                int ar = wm*32 + mf*16 + (lane & 15);
                uint32_t off = (uint32_t)(ar*128 + (((2*kk + ahalf) ^ (ar & 7)) << 4));
                ldm4(qh4[mf], sb + QH + off);
                ldm4(ql4[mf], sb + QL + off);
            }
#pragma unroll
            for (int ng = 0; ng < 4; ng++) {
                int br = wn*64 + ng*16 + ((lane >> 4) << 3) + (lane & 7);
                uint32_t off = (uint32_t)(br*128 + (((2*kk + bhalf) ^ (br & 7)) << 4));
                uint32_t kh4[4], kl4[4];
                ldm4(kh4, st + off);
                ldm4(kl4, st + 16384 + off);
#pragma unroll
                for (int mf = 0; mf < 2; mf++) {
                    mma_f32(sacc[mf][2*ng],   qh4[mf], kh4);
                    mma_f32(sacc[mf][2*ng],   qh4[mf], kl4);
                    mma_f32(sacc[mf][2*ng],   ql4[mf], kh4);
                    mma_f32(sacc[mf][2*ng+1], qh4[mf], kh4 + 2);
                    mma_f32(sacc[mf][2*ng+1], qh4[mf], kl4 + 2);
                    mma_f32(sacc[mf][2*ng+1], ql4[mf], kh4 + 2);
                }
            }
        }

        // ---- causal mask (diagonal tile only) ----
        if (kt == nkt - 1) {
#pragma unroll
            for (int mf = 0; mf < 2; mf++) {
                int r0 = q0 + wm*32 + mf*16 + g, r1 = r0 + 8;
#pragma unroll
                for (int j = 0; j < 8; j++) {
                    int col = k0 + wn*64 + 8*j + t2;
                    if (col     > r0) sacc[mf][j][0] = -1e30f;
                    if (col + 1 > r0) sacc[mf][j][1] = -1e30f;
                    if (col     > r1) sacc[mf][j][2] = -1e30f;
                    if (col + 1 > r1) sacc[mf][j][3] = -1e30f;
                }
            }
        }

        // ---- warp-local max ----
        float tm[2][2] = {{-1e30f, -1e30f}, {-1e30f, -1e30f}};
#pragma unroll
        for (int mf = 0; mf < 2; mf++)
#pragma unroll
            for (int j = 0; j < 8; j++) {
                tm[mf][0] = fmaxf(tm[mf][0], fmaxf(sacc[mf][j][0], sacc[mf][j][1]));
                tm[mf][1] = fmaxf(tm[mf][1], fmaxf(sacc[mf][j][2], sacc[mf][j][3]));
            }
#pragma unroll
        for (int mf = 0; mf < 2; mf++)
#pragma unroll
            for (int i = 0; i < 2; i++) {
                tm[mf][i] = fmaxf(tm[mf][i], __shfl_xor_sync(0xffffffffu, tm[mf][i], 1));
                tm[mf][i] = fmaxf(tm[mf][i], __shfl_xor_sync(0xffffffffu, tm[mf][i], 2));
            }

        // ---- cross-warp max exchange ----
        if ((lane & 3) == 0) {
            sExc[wn*128 + wm*32 + g]           = tm[0][0];
            sExc[wn*128 + wm*32 + g + 8]       = tm[0][1];
            sExc[wn*128 + wm*32 + 16 + g]      = tm[1][0];
            sExc[wn*128 + wm*32 + 16 + g + 8]  = tm[1][1];
        }
        __syncthreads();
        float c[2][2];
#pragma unroll
        for (int mf = 0; mf < 2; mf++)
#pragma unroll
            for (int i = 0; i < 2; i++) {
                float peer = sExc[(1 - wn)*128 + wm*32 + mf*16 + i*8 + g];
                float m2 = fmaxf(mrow[mf][i], fmaxf(tm[mf][i], peer));
                c[mf][i] = exp2f(mrow[mf][i] - m2);
                mrow[mf][i] = m2;
            }

        // ---- exp2 + pack (hi only) + partial sums ----
        float ps[2][2] = {};
        uint32_t pfh[2][4][4];
#pragma unroll
        for (int mf = 0; mf < 2; mf++)
#pragma unroll
            for (int kc = 0; kc < 4; kc++)
#pragma unroll
                for (int jj = 0; jj < 2; jj++) {
                    int j = 2*kc + jj;
                    float p0 = exp2f(sacc[mf][j][0] - mrow[mf][0]);
                    float p1 = exp2f(sacc[mf][j][1] - mrow[mf][0]);
                    float p2 = exp2f(sacc[mf][j][2] - mrow[mf][1]);
                    float p3 = exp2f(sacc[mf][j][3] - mrow[mf][1]);
                    ps[mf][0] += p0 + p1; ps[mf][1] += p2 + p3;
                    pfh[mf][kc][2*jj]   = pk2h(p0, p1);
                    pfh[mf][kc][2*jj+1] = pk2h(p2, p3);
                }
#pragma unroll
        for (int mf = 0; mf < 2; mf++) {
            lsum[mf][0] = lsum[mf][0]*c[mf][0] + ps[mf][0];
            lsum[mf][1] = lsum[mf][1]*c[mf][1] + ps[mf][1];
#pragma unroll
            for (int j = 0; j < 8; j++) {
                oacc[mf][j][0] *= c[mf][0]; oacc[mf][j][1] *= c[mf][0];
                oacc[mf][j][2] *= c[mf][1]; oacc[mf][j][3] *= c[mf][1];
            }
        }

        // ---- O += Ph Vh over this warp's 64 keys ----
#pragma unroll
        for (int kc = 0; kc < 4; kc++)
#pragma unroll
            for (int dg = 0; dg < 4; dg++) {
                int key = wn*64 + kc*16 + 8*(vi & 1) + vr;
                int dc = 2*dg + (vi >> 1);
                uint32_t off = (uint32_t)(key*128 + ((dc ^ (key & 7)) << 4));
                uint32_t vh4[4];
                ldm4t(vh4, st + 32768 + off);
#pragma unroll
                for (int mf = 0; mf < 2; mf++) {
                    mma_f32(oacc[mf][2*dg],   pfh[mf][kc], vh4);
                    mma_f32(oacc[mf][2*dg+1], pfh[mf][kc], vh4 + 2);
                }
            }
        __syncthreads();
    }

    // ---- lsum warp-half reduction ----
#pragma unroll
    for (int mf = 0; mf < 2; mf++)
#pragma unroll
        for (int i = 0; i < 2; i++) {
            lsum[mf][i] += __shfl_xor_sync(0xffffffffu, lsum[mf][i], 1);
            lsum[mf][i] += __shfl_xor_sync(0xffffffffu, lsum[mf][i], 2);
        }

    // ---- merge n-halves (stage-0 smem reuse, stride 65 = conflict-free) ----
    float* sM = (float*)(smraw + ST);
    if (wn == 1) {
        float* dst = sM + (wm*32 + lane) * 65;
#pragma unroll
        for (int mf = 0; mf < 2; mf++)
#pragma unroll
            for (int j = 0; j < 8; j++)
#pragma unroll
                for (int v = 0; v < 4; v++)
                    dst[mf*32 + j*4 + v] = oacc[mf][j][v];
        if ((lane & 3) == 0) {
            sExc[128 + wm*32 + g]           = lsum[0][0];
            sExc[128 + wm*32 + g + 8]       = lsum[0][1];
            sExc[128 + wm*32 + 16 + g]      = lsum[1][0];
            sExc[128 + wm*32 + 16 + g + 8]  = lsum[1][1];
        }
    }
    __syncthreads();
    if (wn == 0) {
        float* src = sM + (wm*32 + lane) * 65;
        float inv[2][2];
#pragma unroll
        for (int mf = 0; mf < 2; mf++)
#pragma unroll
            for (int i = 0; i < 2; i++)
                inv[mf][i] = 1.0f /
                    (lsum[mf][i] + sExc[128 + wm*32 + mf*16 + i*8 + g]);

        int b = bh >> 4, h = bh & 15;
#pragma unroll
        for (int mf = 0; mf < 2; mf++) {
            int r0 = q0 + wm*32 + mf*16 + g, r1 = r0 + 8;
            size_t row0 = (size_t)(b*TT + r0) * CC + h*DD;
            size_t row1 = (size_t)(b*TT + r1) * CC + h*DD;
#pragma unroll
            for (int j = 0; j < 8; j++) {
                float o0 = oacc[mf][j][0] + src[mf*32 + j*4 + 0];
                float o1 = oacc[mf][j][1] + src[mf*32 + j*4 + 1];
                float o2 = oacc[mf][j][2] + src[mf*32 + j*4 + 2];
                float o3 = oacc[mf][j][3] + src[mf*32 + j*4 + 3];
                int d = 8*j + t2;
                *(uint32_t*)(g_ah + row0 + d) = pk2h(o0*inv[mf][0], o1*inv[mf][0]);
                *(uint32_t*)(g_ah + row1 + d) = pk2h(o2*inv[mf][1], o3*inv[mf][1]);
            }
        }
    }
}

// ---------------------------------------------------------------------------
extern "C" void kernel_launch(void* const* d_in, const int* in_sizes, int n_in,
                              void* d_out, int out_size)
{
    (void)in_sizes; (void)n_in; (void)out_size;
    const float* x  = (const float*)d_in[0];
    const float* Wq = (const float*)d_in[1];
    const float* bq = (const float*)d_in[2];
    const float* Wk = (const float*)d_in[3];
    const float* bk = (const float*)d_in[4];
    const float* Wv = (const float*)d_in[5];
    const float* bv = (const float*)d_in[6];
    const float* Wo = (const float*)d_in[7];
    const float* bo = (const float*)d_in[8];
    float* out = (float*)d_out;

    h16 *xh, *xl, *ah, *wh, *wl, *qh, *ql, *kh, *kl, *vh;
    cudaGetSymbolAddress((void**)&xh, g_xh);
    cudaGetSymbolAddress((void**)&xl, g_xl);
    cudaGetSymbolAddress((void**)&ah, g_ah);
    cudaGetSymbolAddress((void**)&wh, g_wh);
    cudaGetSymbolAddress((void**)&wl, g_wl);
    cudaGetSymbolAddress((void**)&qh, g_qh);
    cudaGetSymbolAddress((void**)&ql, g_ql);
    cudaGetSymbolAddress((void**)&kh, g_kh);
    cudaGetSymbolAddress((void**)&kl, g_kl);
    cudaGetSymbolAddress((void**)&vh, g_vh);

    // 1. split x
    split_kernel<<<(MM*CC/4)/256, 256>>>(x, xh, xl);

    // 2. transpose+split all 4 weights (one launch)
    tsplit_kernel<<<dim3(CC/32, CC/32, 4), dim3(32, 8)>>>(Wq, Wk, Wv, Wo, wh, wl);

    const int gsm3 = 2 * 65536;  // 128 KB
    const int gsm1 = 2 * 32768;  //  64 KB
    cudaFuncSetAttribute(gemm_f16<0,3>, cudaFuncAttributeMaxDynamicSharedMemorySize, gsm3);
    cudaFuncSetAttribute(gemm_f16<1,1>, cudaFuncAttributeMaxDynamicSharedMemorySize, gsm1);
    cudaFuncSetAttribute(gemm_f16<2,1>, cudaFuncAttributeMaxDynamicSharedMemorySize, gsm1);

    // 3a. QK fused projection (N=2048, x3); Q pre-scaled by log2e/8
    gemm_f16<0,3><<<dim3(2*CC/128, MM/128), 256, gsm3>>>(
        xh, xl, wh, wl, bq, bk, nullptr, qh, ql, kh, kl);

    // 3b. V projection (x1, hi-only)
    gemm_f16<1,1><<<dim3(CC/128, MM/128), 256, gsm1>>>(
        xh, nullptr, wh + (size_t)2*CC*CC, nullptr, bv, nullptr,
        nullptr, vh, nullptr, nullptr, nullptr);

    // 4. tensor-core flash attention (4m x 2n, PV = Ph*Vh)
    const int asm_sz = 32768 + 2*49152 + 1024;
    cudaFuncSetAttribute(attn_mma, cudaFuncAttributeMaxDynamicSharedMemorySize, asm_sz);
    attn_mma<<<dim3(TT/128, BB*HH), 256, asm_sz>>>();

    // 5. output projection (x1) -> d_out (fp32)
    gemm_f16<2,1><<<dim3(CC/128, MM/128), 256, gsm1>>>(
        ah, nullptr, wh + (size_t)3*CC*CC, nullptr, bo, nullptr,
        out, nullptr, nullptr, nullptr, nullptr);
}